// round 1
// baseline (speedup 1.0000x reference)
#include <cuda_runtime.h>
#include <mma.h>

using namespace nvcuda;

namespace {
constexpr int NE = 8;      // experts
constexpr int NM = 2048;   // tokens per expert (B*C)
constexpr int NH = 2048;   // hidden dim
constexpr int NF = 7168;   // ffn dim

constexpr int BK  = 32;
constexpr int BM1 = 128, BN1 = 64;    // gemm1 tile (dual accumulators)
constexpr int BM2 = 128, BN2 = 128;   // gemm2 tile

constexpr int SA_LD  = BK + 8;        // 40 floats (160B, mult of 16B)
constexpr int SB1_LD = BN1 + 8;       // 72 floats
constexpr int SB2_LD = BN2 + 8;       // 136 floats
}

// Scratch for the fused SwiGLU intermediate: hidden[e][m][f], fp32.
// 8 * 2048 * 7168 * 4B = 448 MiB, static device allocation (no cudaMalloc).
__device__ float g_hidden[(size_t)NE * NM * NF];

// ---------------------------------------------------------------------------
// Kernel 1: per-expert  t1 = X*W1, t3 = X*W3, hidden = silu(t1)*t3
//   X  : [NM, NH] row-major   (per expert)
//   W1 : [NH, NF] row-major
//   W3 : [NH, NF] row-major
// grid: (NF/BN1, NM/BM1, NE), block: 256 (8 warps, 4x2 warp grid, 32x32/warp)
// ---------------------------------------------------------------------------
__global__ void __launch_bounds__(256, 1)
swiglu_gemm1(const float* __restrict__ X,
             const float* __restrict__ W1,
             const float* __restrict__ W3) {
    const int e  = blockIdx.z;
    const int m0 = blockIdx.y * BM1;
    const int n0 = blockIdx.x * BN1;

    const float* A  = X  + (size_t)e * NM * NH;
    const float* B1 = W1 + (size_t)e * NH * NF;
    const float* B3 = W3 + (size_t)e * NH * NF;
    float* Hout = g_hidden + (size_t)e * NM * NF;

    __shared__ float sA [BM1][SA_LD];
    __shared__ float sB1[BK ][SB1_LD];
    __shared__ float sB3[BK ][SB1_LD];

    const int tid  = threadIdx.x;
    const int warp = tid >> 5;
    const int wm   = warp >> 1;   // 0..3 -> rows wm*32
    const int wn   = warp & 1;    // 0..1 -> cols wn*32

    wmma::fragment<wmma::accumulator, 16, 16, 8, float> c1[2][2], c3[2][2];
#pragma unroll
    for (int i = 0; i < 2; i++)
#pragma unroll
        for (int j = 0; j < 2; j++) {
            wmma::fill_fragment(c1[i][j], 0.0f);
            wmma::fill_fragment(c3[i][j], 0.0f);
        }

    for (int kt = 0; kt < NH; kt += BK) {
        // Stage A tile: 128x32 floats = 1024 float4, 4 per thread.
#pragma unroll
        for (int it = 0; it < 4; it++) {
            int idx = tid + it * 256;
            int row = idx >> 3;             // 8 float4 per row
            int c4  = (idx & 7) << 2;
            float4 v = *reinterpret_cast<const float4*>(
                A + (size_t)(m0 + row) * NH + kt + c4);
            sA[row][c4 + 0] = wmma::__float_to_tf32(v.x);
            sA[row][c4 + 1] = wmma::__float_to_tf32(v.y);
            sA[row][c4 + 2] = wmma::__float_to_tf32(v.z);
            sA[row][c4 + 3] = wmma::__float_to_tf32(v.w);
        }
        // Stage B1/B3 tiles: 32x64 floats = 512 float4 each, 2 per thread.
#pragma unroll
        for (int it = 0; it < 2; it++) {
            int idx = tid + it * 256;
            int row = idx >> 4;             // 16 float4 per row
            int c4  = (idx & 15) << 2;
            size_t g = (size_t)(kt + row) * NF + n0 + c4;
            float4 v1 = *reinterpret_cast<const float4*>(B1 + g);
            float4 v3 = *reinterpret_cast<const float4*>(B3 + g);
            sB1[row][c4 + 0] = wmma::__float_to_tf32(v1.x);
            sB1[row][c4 + 1] = wmma::__float_to_tf32(v1.y);
            sB1[row][c4 + 2] = wmma::__float_to_tf32(v1.z);
            sB1[row][c4 + 3] = wmma::__float_to_tf32(v1.w);
            sB3[row][c4 + 0] = wmma::__float_to_tf32(v3.x);
            sB3[row][c4 + 1] = wmma::__float_to_tf32(v3.y);
            sB3[row][c4 + 2] = wmma::__float_to_tf32(v3.z);
            sB3[row][c4 + 3] = wmma::__float_to_tf32(v3.w);
        }
        __syncthreads();

#pragma unroll
        for (int kk = 0; kk < BK; kk += 8) {
            wmma::fragment<wmma::matrix_a, 16, 16, 8, wmma::precision::tf32,
                           wmma::row_major> a[2];
            wmma::fragment<wmma::matrix_b, 16, 16, 8, wmma::precision::tf32,
                           wmma::row_major> b1f[2], b3f[2];
#pragma unroll
            for (int i = 0; i < 2; i++)
                wmma::load_matrix_sync(a[i], &sA[wm * 32 + i * 16][kk], SA_LD);
#pragma unroll
            for (int j = 0; j < 2; j++) {
                wmma::load_matrix_sync(b1f[j], &sB1[kk][wn * 32 + j * 16], SB1_LD);
                wmma::load_matrix_sync(b3f[j], &sB3[kk][wn * 32 + j * 16], SB1_LD);
            }
#pragma unroll
            for (int i = 0; i < 2; i++)
#pragma unroll
                for (int j = 0; j < 2; j++) {
                    wmma::mma_sync(c1[i][j], a[i], b1f[j], c1[i][j]);
                    wmma::mma_sync(c3[i][j], a[i], b3f[j], c3[i][j]);
                }
        }
        __syncthreads();
    }

    // SwiGLU epilogue: both accumulators share the same lane->element mapping,
    // so silu(c1)*c3 is purely elementwise in registers.
#pragma unroll
    for (int i = 0; i < 2; i++)
#pragma unroll
        for (int j = 0; j < 2; j++) {
#pragma unroll
            for (int t = 0; t < c1[i][j].num_elements; t++) {
                float x = c1[i][j].x[t];
                float s = x / (1.0f + __expf(-x));
                c1[i][j].x[t] = s * c3[i][j].x[t];
            }
            wmma::store_matrix_sync(
                Hout + (size_t)(m0 + wm * 32 + i * 16) * NF + n0 + wn * 32 + j * 16,
                c1[i][j], NF, wmma::mem_row_major);
        }
}

// ---------------------------------------------------------------------------
// Kernel 2: per-expert  out = hidden * W2
//   hidden : [NM, NF] row-major
//   W2     : [NF, NH] row-major
// grid: (NH/BN2, NM/BM2, NE), block: 256 (8 warps, 4x2 warp grid, 32x64/warp)
// ---------------------------------------------------------------------------
__global__ void __launch_bounds__(256, 1)
swiglu_gemm2(const float* __restrict__ W2, float* __restrict__ Out) {
    const int e  = blockIdx.z;
    const int m0 = blockIdx.y * BM2;
    const int n0 = blockIdx.x * BN2;

    const float* A = g_hidden + (size_t)e * NM * NF;
    const float* B = W2 + (size_t)e * NF * NH;
    float* C = Out + (size_t)e * NM * NH;

    __shared__ float sA[BM2][SA_LD];
    __shared__ float sB[BK ][SB2_LD];

    const int tid  = threadIdx.x;
    const int warp = tid >> 5;
    const int wm   = warp >> 1;   // 0..3 -> rows wm*32
    const int wn   = warp & 1;    // 0..1 -> cols wn*64

    wmma::fragment<wmma::accumulator, 16, 16, 8, float> c[2][4];
#pragma unroll
    for (int i = 0; i < 2; i++)
#pragma unroll
        for (int j = 0; j < 4; j++)
            wmma::fill_fragment(c[i][j], 0.0f);

    for (int kt = 0; kt < NF; kt += BK) {
        // Stage A tile: 128x32 floats = 1024 float4, 4 per thread.
#pragma unroll
        for (int it = 0; it < 4; it++) {
            int idx = tid + it * 256;
            int row = idx >> 3;
            int c4  = (idx & 7) << 2;
            float4 v = *reinterpret_cast<const float4*>(
                A + (size_t)(m0 + row) * NF + kt + c4);
            sA[row][c4 + 0] = wmma::__float_to_tf32(v.x);
            sA[row][c4 + 1] = wmma::__float_to_tf32(v.y);
            sA[row][c4 + 2] = wmma::__float_to_tf32(v.z);
            sA[row][c4 + 3] = wmma::__float_to_tf32(v.w);
        }
        // Stage B tile: 32x128 floats = 1024 float4, 4 per thread.
#pragma unroll
        for (int it = 0; it < 4; it++) {
            int idx = tid + it * 256;
            int row = idx >> 5;             // 32 float4 per row
            int c4  = (idx & 31) << 2;
            float4 v = *reinterpret_cast<const float4*>(
                B + (size_t)(kt + row) * NH + n0 + c4);
            sB[row][c4 + 0] = wmma::__float_to_tf32(v.x);
            sB[row][c4 + 1] = wmma::__float_to_tf32(v.y);
            sB[row][c4 + 2] = wmma::__float_to_tf32(v.z);
            sB[row][c4 + 3] = wmma::__float_to_tf32(v.w);
        }
        __syncthreads();

#pragma unroll
        for (int kk = 0; kk < BK; kk += 8) {
            wmma::fragment<wmma::matrix_a, 16, 16, 8, wmma::precision::tf32,
                           wmma::row_major> a[2];
            wmma::fragment<wmma::matrix_b, 16, 16, 8, wmma::precision::tf32,
                           wmma::row_major> b[4];
#pragma unroll
            for (int i = 0; i < 2; i++)
                wmma::load_matrix_sync(a[i], &sA[wm * 32 + i * 16][kk], SA_LD);
#pragma unroll
            for (int j = 0; j < 4; j++)
                wmma::load_matrix_sync(b[j], &sB[kk][wn * 64 + j * 16], SB2_LD);
#pragma unroll
            for (int i = 0; i < 2; i++)
#pragma unroll
                for (int j = 0; j < 4; j++)
                    wmma::mma_sync(c[i][j], a[i], b[j], c[i][j]);
        }
        __syncthreads();
    }

#pragma unroll
    for (int i = 0; i < 2; i++)
#pragma unroll
        for (int j = 0; j < 4; j++)
            wmma::store_matrix_sync(
                C + (size_t)(m0 + wm * 32 + i * 16) * NH + n0 + wn * 64 + j * 16,
                c[i][j], NH, wmma::mem_row_major);
}

// ---------------------------------------------------------------------------
// Launch
// ---------------------------------------------------------------------------
extern "C" void kernel_launch(void* const* d_in, const int* in_sizes, int n_in,
                              void* d_out, int out_size) {
    const float* x  = (const float*)d_in[0];   // dispatch_input (E,B,C,H)
    const float* w1 = (const float*)d_in[1];   // (E,H,F)
    const float* w2 = (const float*)d_in[2];   // (E,F,H)
    const float* w3 = (const float*)d_in[3];   // (E,H,F)
    float* out = (float*)d_out;                // (E,B,C,H)

    dim3 g1(NF / BN1, NM / BM1, NE);           // 112 x 16 x 8
    swiglu_gemm1<<<g1, 256>>>(x, w1, w3);

    dim3 g2(NH / BN2, NM / BM2, NE);           // 16 x 16 x 8
    swiglu_gemm2<<<g2, 256>>>(w2, out);
}

// round 2
// speedup vs baseline: 1.1732x; 1.1732x over previous
#include <cuda_runtime.h>
#include <mma.h>
#include <cstdint>

using namespace nvcuda;

namespace {
constexpr int NE = 8;      // experts
constexpr int NM = 2048;   // tokens per expert (B*C)
constexpr int NH = 2048;   // hidden dim
constexpr int NF = 7168;   // ffn dim

constexpr int BM = 128, BN = 128, BK = 32;
constexpr int STAGES = 3;
constexpr int NT = 256;    // threads per block (8 warps: 4x2)

constexpr int A_LD = BK + 4;         // 36 floats
constexpr int B_LD = BN + 4;         // 132 floats
constexpr int A_SZ = BM * A_LD;      // 4608 floats
constexpr int B_SZ = BK * B_LD;      // 4224 floats
constexpr int ST1  = A_SZ + 2 * B_SZ; // 13056 floats per stage (gemm1: B1+B3)
constexpr int ST2  = A_SZ + B_SZ;     // 8832 floats per stage (gemm2)
constexpr unsigned SMEM1 = ST1 * STAGES * 4; // 156672 B
constexpr unsigned SMEM2 = ST2 * STAGES * 4; // 105984 B
}

// Static scratch (no cudaMalloc allowed): tf32-rounded operand copies + hidden.
__device__ float g_xc [(size_t)NE * NM * NH];
__device__ float g_w1c[(size_t)NE * NH * NF];
__device__ float g_w3c[(size_t)NE * NH * NF];
__device__ float g_w2c[(size_t)NE * NF * NH];
__device__ float g_hidden[(size_t)NE * NM * NF];

// ---------------------------------------------------------------------------
// cp.async helpers
// ---------------------------------------------------------------------------
__device__ __forceinline__ void cp16(float* dst, const float* src) {
    uint32_t d = (uint32_t)__cvta_generic_to_shared(dst);
    asm volatile("cp.async.cg.shared.global [%0], [%1], 16;\n" :: "r"(d), "l"(src));
}
__device__ __forceinline__ void cp_commit() {
    asm volatile("cp.async.commit_group;\n");
}
template <int N>
__device__ __forceinline__ void cp_wait() {
    asm volatile("cp.async.wait_group %0;\n" :: "n"(N));
}

// ---------------------------------------------------------------------------
// RNE fp32 -> tf32 pre-conversion (hoists conversion off the GEMM mainloop)
// ---------------------------------------------------------------------------
__global__ void convert_tf32(const float4* __restrict__ src,
                             float4* __restrict__ dst, int n4) {
    int i = blockIdx.x * blockDim.x + threadIdx.x;
    if (i >= n4) return;
    float4 v = src[i];
    v.x = wmma::__float_to_tf32(v.x);
    v.y = wmma::__float_to_tf32(v.y);
    v.z = wmma::__float_to_tf32(v.z);
    v.w = wmma::__float_to_tf32(v.w);
    dst[i] = v;
}

// ---------------------------------------------------------------------------
// Kernel 1: hidden = silu(X*W1) * (X*W3)   (all operands pre-converted tf32)
// grid: (NF/BN, NM/BM, NE), block 256, warp tile 32x64, dual accumulators
// ---------------------------------------------------------------------------
__global__ void __launch_bounds__(NT)
swiglu_gemm1() {
    extern __shared__ float sm[];
    const int e  = blockIdx.z;
    const int m0 = blockIdx.y * BM;
    const int n0 = blockIdx.x * BN;

    const float* A  = g_xc  + (size_t)e * NM * NH;
    const float* B1 = g_w1c + (size_t)e * NH * NF;
    const float* B3 = g_w3c + (size_t)e * NH * NF;
    float* H = g_hidden + (size_t)e * NM * NF;

    const int tid  = threadIdx.x;
    const int warp = tid >> 5;
    const int wm   = warp >> 1;   // 0..3
    const int wn   = warp & 1;    // 0..1

    const int a_row = tid >> 3,  a_c4 = (tid & 7)  << 2;
    const int b_row = tid >> 5,  b_c4 = (tid & 31) << 2;

    wmma::fragment<wmma::accumulator, 16, 16, 8, float> c1[2][4], c3[2][4];
#pragma unroll
    for (int i = 0; i < 2; i++)
#pragma unroll
        for (int j = 0; j < 4; j++) {
            wmma::fill_fragment(c1[i][j], 0.0f);
            wmma::fill_fragment(c3[i][j], 0.0f);
        }

    auto stage_load = [&](int st, int kt) {
        float* sA  = sm + st * ST1;
        float* sB1 = sA + A_SZ;
        float* sB3 = sB1 + B_SZ;
#pragma unroll
        for (int it = 0; it < 4; it++) {
            int row = a_row + it * 32;
            cp16(sA + row * A_LD + a_c4,
                 A + (size_t)(m0 + row) * NH + kt + a_c4);
        }
#pragma unroll
        for (int it = 0; it < 4; it++) {
            int row = b_row + it * 8;
            size_t g = (size_t)(kt + row) * NF + n0 + b_c4;
            cp16(sB1 + row * B_LD + b_c4, B1 + g);
            cp16(sB3 + row * B_LD + b_c4, B3 + g);
        }
    };

    constexpr int NIT = NH / BK;   // 64
    stage_load(0, 0);  cp_commit();
    stage_load(1, BK); cp_commit();

    for (int it = 0; it < NIT; it++) {
        cp_wait<STAGES - 2>();
        __syncthreads();

        // prefetch tile it+2 into slot (it+2)%3 (last read at iter it-1; the
        // barrier above guarantees all warps finished that read)
        int nt = it + STAGES - 1;
        if (nt < NIT) stage_load(nt % STAGES, nt * BK);
        cp_commit();

        const float* sA  = sm + (it % STAGES) * ST1;
        const float* sB1 = sA + A_SZ;
        const float* sB3 = sB1 + B_SZ;

#pragma unroll
        for (int kk = 0; kk < BK; kk += 8) {
            wmma::fragment<wmma::matrix_a, 16, 16, 8, wmma::precision::tf32,
                           wmma::row_major> a[2];
            wmma::fragment<wmma::matrix_b, 16, 16, 8, wmma::precision::tf32,
                           wmma::row_major> bf[4];
#pragma unroll
            for (int i = 0; i < 2; i++)
                wmma::load_matrix_sync(a[i], sA + (wm * 32 + i * 16) * A_LD + kk, A_LD);
#pragma unroll
            for (int j = 0; j < 4; j++)
                wmma::load_matrix_sync(bf[j], sB1 + kk * B_LD + wn * 64 + j * 16, B_LD);
#pragma unroll
            for (int i = 0; i < 2; i++)
#pragma unroll
                for (int j = 0; j < 4; j++)
                    wmma::mma_sync(c1[i][j], a[i], bf[j], c1[i][j]);
#pragma unroll
            for (int j = 0; j < 4; j++)
                wmma::load_matrix_sync(bf[j], sB3 + kk * B_LD + wn * 64 + j * 16, B_LD);
#pragma unroll
            for (int i = 0; i < 2; i++)
#pragma unroll
                for (int j = 0; j < 4; j++)
                    wmma::mma_sync(c3[i][j], a[i], bf[j], c3[i][j]);
        }
    }

    // SwiGLU epilogue; store hidden pre-rounded to tf32 so gemm2 skips conversion.
#pragma unroll
    for (int i = 0; i < 2; i++)
#pragma unroll
        for (int j = 0; j < 4; j++) {
#pragma unroll
            for (int t = 0; t < c1[i][j].num_elements; t++) {
                float x = c1[i][j].x[t];
                float s = x / (1.0f + __expf(-x));
                c1[i][j].x[t] = wmma::__float_to_tf32(s * c3[i][j].x[t]);
            }
            wmma::store_matrix_sync(
                H + (size_t)(m0 + wm * 32 + i * 16) * NF + n0 + wn * 64 + j * 16,
                c1[i][j], NF, wmma::mem_row_major);
        }
}

// ---------------------------------------------------------------------------
// Kernel 2: out = hidden * W2
// grid: (NH/BN, NM/BM, NE), block 256, warp tile 32x64
// ---------------------------------------------------------------------------
__global__ void __launch_bounds__(NT)
swiglu_gemm2(float* __restrict__ Out) {
    extern __shared__ float sm[];
    const int e  = blockIdx.z;
    const int m0 = blockIdx.y * BM;
    const int n0 = blockIdx.x * BN;

    const float* A = g_hidden + (size_t)e * NM * NF;
    const float* B = g_w2c    + (size_t)e * NF * NH;
    float* C = Out + (size_t)e * NM * NH;

    const int tid  = threadIdx.x;
    const int warp = tid >> 5;
    const int wm   = warp >> 1;
    const int wn   = warp & 1;

    const int a_row = tid >> 3,  a_c4 = (tid & 7)  << 2;
    const int b_row = tid >> 5,  b_c4 = (tid & 31) << 2;

    wmma::fragment<wmma::accumulator, 16, 16, 8, float> c[2][4];
#pragma unroll
    for (int i = 0; i < 2; i++)
#pragma unroll
        for (int j = 0; j < 4; j++)
            wmma::fill_fragment(c[i][j], 0.0f);

    auto stage_load = [&](int st, int kt) {
        float* sA = sm + st * ST2;
        float* sB = sA + A_SZ;
#pragma unroll
        for (int it = 0; it < 4; it++) {
            int row = a_row + it * 32;
            cp16(sA + row * A_LD + a_c4,
                 A + (size_t)(m0 + row) * NF + kt + a_c4);
        }
#pragma unroll
        for (int it = 0; it < 4; it++) {
            int row = b_row + it * 8;
            cp16(sB + row * B_LD + b_c4,
                 B + (size_t)(kt + row) * NH + n0 + b_c4);
        }
    };

    constexpr int NIT = NF / BK;   // 224
    stage_load(0, 0);  cp_commit();
    stage_load(1, BK); cp_commit();

    for (int it = 0; it < NIT; it++) {
        cp_wait<STAGES - 2>();
        __syncthreads();

        int nt = it + STAGES - 1;
        if (nt < NIT) stage_load(nt % STAGES, nt * BK);
        cp_commit();

        const float* sA = sm + (it % STAGES) * ST2;
        const float* sB = sA + A_SZ;

#pragma unroll
        for (int kk = 0; kk < BK; kk += 8) {
            wmma::fragment<wmma::matrix_a, 16, 16, 8, wmma::precision::tf32,
                           wmma::row_major> a[2];
            wmma::fragment<wmma::matrix_b, 16, 16, 8, wmma::precision::tf32,
                           wmma::row_major> b[4];
#pragma unroll
            for (int i = 0; i < 2; i++)
                wmma::load_matrix_sync(a[i], sA + (wm * 32 + i * 16) * A_LD + kk, A_LD);
#pragma unroll
            for (int j = 0; j < 4; j++)
                wmma::load_matrix_sync(b[j], sB + kk * B_LD + wn * 64 + j * 16, B_LD);
#pragma unroll
            for (int i = 0; i < 2; i++)
#pragma unroll
                for (int j = 0; j < 4; j++)
                    wmma::mma_sync(c[i][j], a[i], b[j], c[i][j]);
        }
    }

#pragma unroll
    for (int i = 0; i < 2; i++)
#pragma unroll
        for (int j = 0; j < 4; j++)
            wmma::store_matrix_sync(
                C + (size_t)(m0 + wm * 32 + i * 16) * NH + n0 + wn * 64 + j * 16,
                c[i][j], NH, wmma::mem_row_major);
}

// ---------------------------------------------------------------------------
// Launch
// ---------------------------------------------------------------------------
extern "C" void kernel_launch(void* const* d_in, const int* in_sizes, int n_in,
                              void* d_out, int out_size) {
    const float* x  = (const float*)d_in[0];   // (E,B,C,H)
    const float* w1 = (const float*)d_in[1];   // (E,H,F)
    const float* w2 = (const float*)d_in[2];   // (E,F,H)
    const float* w3 = (const float*)d_in[3];   // (E,H,F)
    float* out = (float*)d_out;                // (E,B,C,H)

    cudaFuncSetAttribute(swiglu_gemm1,
                         cudaFuncAttributeMaxDynamicSharedMemorySize, SMEM1);
    cudaFuncSetAttribute(swiglu_gemm2,
                         cudaFuncAttributeMaxDynamicSharedMemorySize, SMEM2);

    void *pxc, *pw1c, *pw2c, *pw3c;
    cudaGetSymbolAddress(&pxc,  g_xc);
    cudaGetSymbolAddress(&pw1c, g_w1c);
    cudaGetSymbolAddress(&pw2c, g_w2c);
    cudaGetSymbolAddress(&pw3c, g_w3c);

    const int nx4 = NE * NM * NH / 4;   // 8.4M float4
    const int nw4 = NE * NH * NF / 4;   // 29.4M float4
    convert_tf32<<<(nx4 + 255) / 256, 256>>>((const float4*)x,  (float4*)pxc,  nx4);
    convert_tf32<<<(nw4 + 255) / 256, 256>>>((const float4*)w1, (float4*)pw1c, nw4);
    convert_tf32<<<(nw4 + 255) / 256, 256>>>((const float4*)w3, (float4*)pw3c, nw4);
    convert_tf32<<<(nw4 + 255) / 256, 256>>>((const float4*)w2, (float4*)pw2c, nw4);

    dim3 g1(NF / BN, NM / BM, NE);   // 56 x 16 x 8
    swiglu_gemm1<<<g1, NT, SMEM1>>>();

    dim3 g2(NH / BN, NM / BM, NE);   // 16 x 16 x 8
    swiglu_gemm2<<<g2, NT, SMEM2>>>(out);
}

// round 5
// speedup vs baseline: 1.2187x; 1.0388x over previous
#include <cuda_runtime.h>
#include <mma.h>
#include <cstdint>

using namespace nvcuda;

namespace {
constexpr int NE = 8, NM = 2048, NH = 2048, NF = 7168;

constexpr int BM = 128, BN = 128, BK = 32;
constexpr int STAGES = 3;
constexpr int NT = 256;              // 8 warps, 4x2 grid, warp tile 32x64

constexpr int A_LD = BK + 8;         // 40 floats (160B rows, 16B aligned)
constexpr int B_LD = BN + 4;         // 132 floats (528B rows, 16B aligned)
constexpr int A_SZ = BM * A_LD;      // 5120 floats
constexpr int B_SZ = BK * B_LD;      // 4224 floats
constexpr int STG  = A_SZ + B_SZ;    // 9344 floats = 37376 B
constexpr unsigned SMEM = STG * STAGES * 4;   // 112128 B  (2 CTAs fit 228KB/SM)
}

// ---------------------------------------------------------------------------
// Static device scratch (no cudaMalloc allowed)
// ---------------------------------------------------------------------------
__device__ float g_xc [(size_t)NE * NM * NH];   // x  tf32-rounded [M,H]
__device__ float g_w1c[(size_t)NE * NH * NF];   // w1 tf32-rounded [H,F]
__device__ float g_w3c[(size_t)NE * NH * NF];   // w3 tf32-rounded [H,F]
__device__ float g_w2c[(size_t)NE * NF * NH];   // w2 tf32-rounded [F,H]
__device__ float g_t1 [(size_t)NE * NM * NF];   // x*w1
__device__ float g_t3 [(size_t)NE * NM * NF];   // x*w3
__device__ float g_hid[(size_t)NE * NM * NF];   // silu(t1)*t3, tf32-rounded

// ---------------------------------------------------------------------------
// helpers
// ---------------------------------------------------------------------------
__device__ __forceinline__ float rnd_tf32(float v) {
    // RNE fp32 -> tf32 rounding via the wmma intrinsic (lowers to cvt.rna.tf32)
    return wmma::__float_to_tf32(v);
}
__device__ __forceinline__ void cp16(float* dst, const float* src) {
    uint32_t d = (uint32_t)__cvta_generic_to_shared(dst);
    asm volatile("cp.async.cg.shared.global [%0], [%1], 16;\n" :: "r"(d), "l"(src));
}
__device__ __forceinline__ void cp_commit() {
    asm volatile("cp.async.commit_group;\n");
}
template <int N> __device__ __forceinline__ void cp_wait() {
    asm volatile("cp.async.wait_group %0;\n" :: "n"(N));
}

// ---------------------------------------------------------------------------
// fp32 -> tf32 pre-rounding (hoists conversion off the GEMM mainloop)
// ---------------------------------------------------------------------------
__global__ void conv_tf32(const float4* __restrict__ in,
                          float4* __restrict__ out, int n4) {
    int i = blockIdx.x * blockDim.x + threadIdx.x;
    if (i >= n4) return;
    float4 v = in[i];
    v.x = rnd_tf32(v.x); v.y = rnd_tf32(v.y);
    v.z = rnd_tf32(v.z); v.w = rnd_tf32(v.w);
    out[i] = v;
}

// ---------------------------------------------------------------------------
// SwiGLU elementwise: hid = tf32_round( silu(t1) * t3 )
// ---------------------------------------------------------------------------
__global__ void swiglu_ew(const float4* __restrict__ t1,
                          const float4* __restrict__ t3,
                          float4* __restrict__ h, int n4) {
    int i = blockIdx.x * blockDim.x + threadIdx.x;
    if (i >= n4) return;
    float4 a = t1[i], b = t3[i], o;
    o.x = rnd_tf32(a.x / (1.0f + __expf(-a.x)) * b.x);
    o.y = rnd_tf32(a.y / (1.0f + __expf(-a.y)) * b.y);
    o.z = rnd_tf32(a.z / (1.0f + __expf(-a.z)) * b.z);
    o.w = rnd_tf32(a.w / (1.0f + __expf(-a.w)) * b.w);
    h[i] = o;
}

// ---------------------------------------------------------------------------
// Generic TF32 GEMM: C[e] = A[e] (M x K, row-major) * B[e] (K x N, row-major)
//   grid (NM/BM, N/BN, NE) -- m fast for weight-slice L2 reuse
//   8 warps, warp tile 32x64, 3-stage cp.async pipeline, 2 CTAs/SM
// ---------------------------------------------------------------------------
__global__ void __launch_bounds__(NT, 2)
gemm_tf32(const float* __restrict__ Ag, const float* __restrict__ Bg,
          float* __restrict__ Cg, int N, int K) {
    extern __shared__ float sm[];
    const int e  = blockIdx.z;
    const int m0 = blockIdx.x * BM;
    const int n0 = blockIdx.y * BN;

    const float* A = Ag + (size_t)e * NM * K;
    const float* B = Bg + (size_t)e * K * N;
    float*       C = Cg + (size_t)e * NM * N;

    const int tid  = threadIdx.x;
    const int warp = tid >> 5;
    const int wm   = warp >> 1;   // 0..3 -> rows wm*32
    const int wn   = warp & 1;    // 0..1 -> cols wn*64

    const int a_row = tid >> 3,  a_c4 = (tid & 7)  << 2;
    const int b_row = tid >> 5,  b_c4 = (tid & 31) << 2;

    wmma::fragment<wmma::accumulator, 16, 16, 8, float> c[2][4];
#pragma unroll
    for (int i = 0; i < 2; i++)
#pragma unroll
        for (int j = 0; j < 4; j++)
            wmma::fill_fragment(c[i][j], 0.0f);

    auto fill = [&](int st, int kt) {
        float* sA = sm + st * STG;
        float* sB = sA + A_SZ;
#pragma unroll
        for (int i = 0; i < 4; i++) {
            int row = a_row + i * 32;
            cp16(sA + row * A_LD + a_c4,
                 A + (size_t)(m0 + row) * K + kt + a_c4);
        }
#pragma unroll
        for (int i = 0; i < 4; i++) {
            int row = b_row + i * 8;
            cp16(sB + row * B_LD + b_c4,
                 B + (size_t)(kt + row) * N + n0 + b_c4);
        }
    };

    const int NIT = K / BK;
    fill(0, 0);  cp_commit();
    fill(1, BK); cp_commit();

    for (int it = 0; it < NIT; it++) {
        cp_wait<1>();
        __syncthreads();

        // prefetch stage it+2 (its slot was consumed at iteration it-1;
        // the barrier above guarantees all warps are past that read)
        int nt = it + 2;
        if (nt < NIT) fill(nt % STAGES, nt * BK);
        cp_commit();

        const float* sA = sm + (it % STAGES) * STG;
        const float* sB = sA + A_SZ;

#pragma unroll
        for (int kk = 0; kk < BK; kk += 8) {
            wmma::fragment<wmma::matrix_a, 16, 16, 8, wmma::precision::tf32,
                           wmma::row_major> a[2];
            wmma::fragment<wmma::matrix_b, 16, 16, 8, wmma::precision::tf32,
                           wmma::row_major> b[4];
#pragma unroll
            for (int i = 0; i < 2; i++)
                wmma::load_matrix_sync(a[i], sA + (wm * 32 + i * 16) * A_LD + kk, A_LD);
#pragma unroll
            for (int j = 0; j < 4; j++)
                wmma::load_matrix_sync(b[j], sB + kk * B_LD + wn * 64 + j * 16, B_LD);
#pragma unroll
            for (int i = 0; i < 2; i++)
#pragma unroll
                for (int j = 0; j < 4; j++)
                    wmma::mma_sync(c[i][j], a[i], b[j], c[i][j]);
        }
    }

#pragma unroll
    for (int i = 0; i < 2; i++)
#pragma unroll
        for (int j = 0; j < 4; j++)
            wmma::store_matrix_sync(
                C + (size_t)(m0 + wm * 32 + i * 16) * N + n0 + wn * 64 + j * 16,
                c[i][j], N, wmma::mem_row_major);
}

// ---------------------------------------------------------------------------
// Launch
// ---------------------------------------------------------------------------
extern "C" void kernel_launch(void* const* d_in, const int* in_sizes, int n_in,
                              void* d_out, int out_size) {
    const float* x  = (const float*)d_in[0];   // (E, M, H)
    const float* w1 = (const float*)d_in[1];   // (E, H, F)
    const float* w2 = (const float*)d_in[2];   // (E, F, H)
    const float* w3 = (const float*)d_in[3];   // (E, H, F)
    float* out = (float*)d_out;                // (E, M, H)

    cudaFuncSetAttribute(gemm_tf32,
                         cudaFuncAttributeMaxDynamicSharedMemorySize, SMEM);

    void *pxc, *pw1, *pw2, *pw3, *pt1, *pt3, *ph;
    cudaGetSymbolAddress(&pxc, g_xc);
    cudaGetSymbolAddress(&pw1, g_w1c);
    cudaGetSymbolAddress(&pw2, g_w2c);
    cudaGetSymbolAddress(&pw3, g_w3c);
    cudaGetSymbolAddress(&pt1, g_t1);
    cudaGetSymbolAddress(&pt3, g_t3);
    cudaGetSymbolAddress(&ph,  g_hid);

    const int nx4 = NE * NM * NH / 4;
    const int nw4 = NE * NH * NF / 4;
    conv_tf32<<<(nx4 + 255) / 256, 256>>>((const float4*)x,  (float4*)pxc, nx4);
    conv_tf32<<<(nw4 + 255) / 256, 256>>>((const float4*)w1, (float4*)pw1, nw4);
    conv_tf32<<<(nw4 + 255) / 256, 256>>>((const float4*)w3, (float4*)pw3, nw4);
    conv_tf32<<<(nw4 + 255) / 256, 256>>>((const float4*)w2, (float4*)pw2, nw4);

    // t1 = x*w1, t3 = x*w3   (M=2048, N=7168, K=2048 per expert)
    dim3 g1(NM / BM, NF / BN, NE);   // 16 x 56 x 8
    gemm_tf32<<<g1, NT, SMEM>>>((const float*)pxc, (const float*)pw1,
                                (float*)pt1, NF, NH);
    gemm_tf32<<<g1, NT, SMEM>>>((const float*)pxc, (const float*)pw3,
                                (float*)pt3, NF, NH);

    // hid = tf32( silu(t1) * t3 )
    const int nh4 = NE * NM * NF / 4;
    swiglu_ew<<<(nh4 + 255) / 256, 256>>>((const float4*)pt1, (const float4*)pt3,
                                          (float4*)ph, nh4);

    // out = hid * w2   (M=2048, N=2048, K=7168 per expert)
    dim3 g2(NM / BM, NH / BN, NE);   // 16 x 16 x 8
    gemm_tf32<<<g2, NT, SMEM>>>((const float*)ph, (const float*)pw2,
                                out, NH, NF);
}

// round 6
// speedup vs baseline: 1.2191x; 1.0003x over previous
#include <cuda_runtime.h>
#include <mma.h>
#include <cstdint>

using namespace nvcuda;

namespace {
constexpr int NE = 8, NM = 2048, NH = 2048, NF = 7168;

constexpr int BM = 128, BN = 128, BK = 32;
constexpr int STAGES = 3;
constexpr int NT = 256;              // 8 warps, 4x2 grid, warp tile 32x64

constexpr int A_LD = BK + 8;         // 40 floats (160B rows, 16B aligned)
constexpr int B_LD = BN + 4;         // 132 floats (528B rows, 16B aligned)
constexpr int A_SZ = BM * A_LD;      // 5120 floats
constexpr int B_SZ = BK * B_LD;      // 4224 floats
constexpr int STG  = A_SZ + B_SZ;    // 9344 floats = 37376 B
constexpr unsigned SMEM = STG * STAGES * 4;   // 112128 B  (2 CTAs fit 228KB/SM)
}

// ---------------------------------------------------------------------------
// Static device scratch (no cudaMalloc allowed)
// ---------------------------------------------------------------------------
__device__ float g_xc [(size_t)NE * NM * NH];   // x  tf32-rounded [M,H]
__device__ float g_w1c[(size_t)NE * NH * NF];   // w1 tf32-rounded [H,F]
__device__ float g_w3c[(size_t)NE * NH * NF];   // w3 tf32-rounded [H,F]
__device__ float g_w2c[(size_t)NE * NF * NH];   // w2 tf32-rounded [F,H]
__device__ float g_t1 [(size_t)NE * NM * NF];   // x*w1
__device__ float g_t3 [(size_t)NE * NM * NF];   // x*w3
__device__ float g_hid[(size_t)NE * NM * NF];   // silu(t1)*t3, tf32-rounded

// ---------------------------------------------------------------------------
// helpers
// ---------------------------------------------------------------------------
__device__ __forceinline__ float rnd_tf32(float v) {
    // RNE fp32 -> tf32 rounding via the wmma intrinsic (lowers to cvt.rna.tf32)
    return wmma::__float_to_tf32(v);
}
__device__ __forceinline__ void cp16(float* dst, const float* src) {
    uint32_t d = (uint32_t)__cvta_generic_to_shared(dst);
    asm volatile("cp.async.cg.shared.global [%0], [%1], 16;\n" :: "r"(d), "l"(src));
}
__device__ __forceinline__ void cp_commit() {
    asm volatile("cp.async.commit_group;\n");
}
template <int N> __device__ __forceinline__ void cp_wait() {
    asm volatile("cp.async.wait_group %0;\n" :: "n"(N));
}

// ---------------------------------------------------------------------------
// fp32 -> tf32 pre-rounding (hoists conversion off the GEMM mainloop)
// ---------------------------------------------------------------------------
__global__ void conv_tf32(const float4* __restrict__ in,
                          float4* __restrict__ out, int n4) {
    int i = blockIdx.x * blockDim.x + threadIdx.x;
    if (i >= n4) return;
    float4 v = in[i];
    v.x = rnd_tf32(v.x); v.y = rnd_tf32(v.y);
    v.z = rnd_tf32(v.z); v.w = rnd_tf32(v.w);
    out[i] = v;
}

// ---------------------------------------------------------------------------
// SwiGLU elementwise: hid = tf32_round( silu(t1) * t3 )
// ---------------------------------------------------------------------------
__global__ void swiglu_ew(const float4* __restrict__ t1,
                          const float4* __restrict__ t3,
                          float4* __restrict__ h, int n4) {
    int i = blockIdx.x * blockDim.x + threadIdx.x;
    if (i >= n4) return;
    float4 a = t1[i], b = t3[i], o;
    o.x = rnd_tf32(a.x / (1.0f + __expf(-a.x)) * b.x);
    o.y = rnd_tf32(a.y / (1.0f + __expf(-a.y)) * b.y);
    o.z = rnd_tf32(a.z / (1.0f + __expf(-a.z)) * b.z);
    o.w = rnd_tf32(a.w / (1.0f + __expf(-a.w)) * b.w);
    h[i] = o;
}

// ---------------------------------------------------------------------------
// Generic TF32 GEMM: C[e] = A[e] (M x K, row-major) * B[e] (K x N, row-major)
//   grid (NM/BM, N/BN, NE) -- m fast for weight-slice L2 reuse
//   8 warps, warp tile 32x64, 3-stage cp.async pipeline, 2 CTAs/SM
// ---------------------------------------------------------------------------
__global__ void __launch_bounds__(NT, 2)
gemm_tf32(const float* __restrict__ Ag, const float* __restrict__ Bg,
          float* __restrict__ Cg, int N, int K) {
    extern __shared__ float sm[];
    const int e  = blockIdx.z;
    const int m0 = blockIdx.x * BM;
    const int n0 = blockIdx.y * BN;

    const float* A = Ag + (size_t)e * NM * K;
    const float* B = Bg + (size_t)e * K * N;
    float*       C = Cg + (size_t)e * NM * N;

    const int tid  = threadIdx.x;
    const int warp = tid >> 5;
    const int wm   = warp >> 1;   // 0..3 -> rows wm*32
    const int wn   = warp & 1;    // 0..1 -> cols wn*64

    const int a_row = tid >> 3,  a_c4 = (tid & 7)  << 2;
    const int b_row = tid >> 5,  b_c4 = (tid & 31) << 2;

    wmma::fragment<wmma::accumulator, 16, 16, 8, float> c[2][4];
#pragma unroll
    for (int i = 0; i < 2; i++)
#pragma unroll
        for (int j = 0; j < 4; j++)
            wmma::fill_fragment(c[i][j], 0.0f);

    auto fill = [&](int st, int kt) {
        float* sA = sm + st * STG;
        float* sB = sA + A_SZ;
#pragma unroll
        for (int i = 0; i < 4; i++) {
            int row = a_row + i * 32;
            cp16(sA + row * A_LD + a_c4,
                 A + (size_t)(m0 + row) * K + kt + a_c4);
        }
#pragma unroll
        for (int i = 0; i < 4; i++) {
            int row = b_row + i * 8;
            cp16(sB + row * B_LD + b_c4,
                 B + (size_t)(kt + row) * N + n0 + b_c4);
        }
    };

    const int NIT = K / BK;
    fill(0, 0);  cp_commit();
    fill(1, BK); cp_commit();

    for (int it = 0; it < NIT; it++) {
        cp_wait<1>();
        __syncthreads();

        // prefetch stage it+2 (its slot was consumed at iteration it-1;
        // the barrier above guarantees all warps are past that read)
        int nt = it + 2;
        if (nt < NIT) fill(nt % STAGES, nt * BK);
        cp_commit();

        const float* sA = sm + (it % STAGES) * STG;
        const float* sB = sA + A_SZ;

#pragma unroll
        for (int kk = 0; kk < BK; kk += 8) {
            wmma::fragment<wmma::matrix_a, 16, 16, 8, wmma::precision::tf32,
                           wmma::row_major> a[2];
            wmma::fragment<wmma::matrix_b, 16, 16, 8, wmma::precision::tf32,
                           wmma::row_major> b[4];
#pragma unroll
            for (int i = 0; i < 2; i++)
                wmma::load_matrix_sync(a[i], sA + (wm * 32 + i * 16) * A_LD + kk, A_LD);
#pragma unroll
            for (int j = 0; j < 4; j++)
                wmma::load_matrix_sync(b[j], sB + kk * B_LD + wn * 64 + j * 16, B_LD);
#pragma unroll
            for (int i = 0; i < 2; i++)
#pragma unroll
                for (int j = 0; j < 4; j++)
                    wmma::mma_sync(c[i][j], a[i], b[j], c[i][j]);
        }
    }

#pragma unroll
    for (int i = 0; i < 2; i++)
#pragma unroll
        for (int j = 0; j < 4; j++)
            wmma::store_matrix_sync(
                C + (size_t)(m0 + wm * 32 + i * 16) * N + n0 + wn * 64 + j * 16,
                c[i][j], N, wmma::mem_row_major);
}

// ---------------------------------------------------------------------------
// Launch
// ---------------------------------------------------------------------------
extern "C" void kernel_launch(void* const* d_in, const int* in_sizes, int n_in,
                              void* d_out, int out_size) {
    const float* x  = (const float*)d_in[0];   // (E, M, H)
    const float* w1 = (const float*)d_in[1];   // (E, H, F)
    const float* w2 = (const float*)d_in[2];   // (E, F, H)
    const float* w3 = (const float*)d_in[3];   // (E, H, F)
    float* out = (float*)d_out;                // (E, M, H)

    cudaFuncSetAttribute(gemm_tf32,
                         cudaFuncAttributeMaxDynamicSharedMemorySize, SMEM);

    void *pxc, *pw1, *pw2, *pw3, *pt1, *pt3, *ph;
    cudaGetSymbolAddress(&pxc, g_xc);
    cudaGetSymbolAddress(&pw1, g_w1c);
    cudaGetSymbolAddress(&pw2, g_w2c);
    cudaGetSymbolAddress(&pw3, g_w3c);
    cudaGetSymbolAddress(&pt1, g_t1);
    cudaGetSymbolAddress(&pt3, g_t3);
    cudaGetSymbolAddress(&ph,  g_hid);

    const int nx4 = NE * NM * NH / 4;
    const int nw4 = NE * NH * NF / 4;
    conv_tf32<<<(nx4 + 255) / 256, 256>>>((const float4*)x,  (float4*)pxc, nx4);
    conv_tf32<<<(nw4 + 255) / 256, 256>>>((const float4*)w1, (float4*)pw1, nw4);
    conv_tf32<<<(nw4 + 255) / 256, 256>>>((const float4*)w3, (float4*)pw3, nw4);
    conv_tf32<<<(nw4 + 255) / 256, 256>>>((const float4*)w2, (float4*)pw2, nw4);

    // t1 = x*w1, t3 = x*w3   (M=2048, N=7168, K=2048 per expert)
    dim3 g1(NM / BM, NF / BN, NE);   // 16 x 56 x 8
    gemm_tf32<<<g1, NT, SMEM>>>((const float*)pxc, (const float*)pw1,
                                (float*)pt1, NF, NH);
    gemm_tf32<<<g1, NT, SMEM>>>((const float*)pxc, (const float*)pw3,
                                (float*)pt3, NF, NH);

    // hid = tf32( silu(t1) * t3 )
    const int nh4 = NE * NM * NF / 4;
    swiglu_ew<<<(nh4 + 255) / 256, 256>>>((const float4*)pt1, (const float4*)pt3,
                                          (float4*)ph, nh4);

    // out = hid * w2   (M=2048, N=2048, K=7168 per expert)
    dim3 g2(NM / BM, NH / BN, NE);   // 16 x 16 x 8
    gemm_tf32<<<g2, NT, SMEM>>>((const float*)ph, (const float*)pw2,
                                out, NH, NF);
}

// round 7
// speedup vs baseline: 3.2677x; 2.6804x over previous
#include <cuda_runtime.h>
#include <mma.h>
#include <cstdint>

namespace {
constexpr int NE = 8, NM = 2048, NH = 2048, NF = 7168;

constexpr int BM = 128, BN = 128, BK = 32;
constexpr int STAGES = 3;
constexpr int NT = 256;                    // 8 warps: 4 (m) x 2 (n)

// smem tile: A [128 rows][32 tf32 = 128B], B [128 n-rows][32 tf32 = 128B]
constexpr int TILE_B   = BM * BK * 4;      // 16384 B each
constexpr int STG_B    = 2 * TILE_B;       // 32768 B
constexpr unsigned SMEM = STAGES * STG_B;  // 98304 B (2 CTAs/SM: 192KB)
}

// ---------------------------------------------------------------------------
// Static device scratch (no cudaMalloc allowed)
// ---------------------------------------------------------------------------
__device__ float g_xc [(size_t)NE * NM * NH];   // x  tf32-rounded   [M,K=H]
__device__ float g_w1t[(size_t)NE * NF * NH];   // w1^T tf32-rounded [N=F,K=H]
__device__ float g_w3t[(size_t)NE * NF * NH];   // w3^T tf32-rounded [N=F,K=H]
__device__ float g_w2t[(size_t)NE * NH * NF];   // w2^T tf32-rounded [N=H,K=F]
__device__ float g_t1 [(size_t)NE * NM * NF];   // x*w1
__device__ float g_t3 [(size_t)NE * NM * NF];   // x*w3
__device__ float g_hid[(size_t)NE * NM * NF];   // silu(t1)*t3, tf32-rounded

// ---------------------------------------------------------------------------
// helpers
// ---------------------------------------------------------------------------
__device__ __forceinline__ float rnd_tf32(float v) {
    return nvcuda::wmma::__float_to_tf32(v);   // cvt.rna.tf32.f32
}
__device__ __forceinline__ void cp16(uint32_t dst, const float* src) {
    asm volatile("cp.async.cg.shared.global [%0], [%1], 16;\n" :: "r"(dst), "l"(src));
}
__device__ __forceinline__ void cp_commit() {
    asm volatile("cp.async.commit_group;\n");
}
template <int N> __device__ __forceinline__ void cp_wait() {
    asm volatile("cp.async.wait_group %0;\n" :: "n"(N));
}
__device__ __forceinline__ void ldm4(uint32_t& r0, uint32_t& r1,
                                     uint32_t& r2, uint32_t& r3, uint32_t addr) {
    asm volatile("ldmatrix.sync.aligned.m8n8.x4.shared.b16 {%0,%1,%2,%3}, [%4];"
                 : "=r"(r0), "=r"(r1), "=r"(r2), "=r"(r3) : "r"(addr));
}
__device__ __forceinline__ void mma_tf32(float* c, uint32_t a0, uint32_t a1,
                                         uint32_t a2, uint32_t a3,
                                         uint32_t b0, uint32_t b1) {
    asm volatile(
        "mma.sync.aligned.m16n8k8.row.col.f32.tf32.tf32.f32 "
        "{%0,%1,%2,%3}, {%4,%5,%6,%7}, {%8,%9}, {%0,%1,%2,%3};"
        : "+f"(c[0]), "+f"(c[1]), "+f"(c[2]), "+f"(c[3])
        : "r"(a0), "r"(a1), "r"(a2), "r"(a3), "r"(b0), "r"(b1));
}

// ---------------------------------------------------------------------------
// fp32 -> tf32 pre-round (elementwise) and round+transpose (weights -> [N,K])
// ---------------------------------------------------------------------------
__global__ void conv_x(const float4* __restrict__ in, float4* __restrict__ out,
                       int n4) {
    int i = blockIdx.x * blockDim.x + threadIdx.x;
    if (i >= n4) return;
    float4 v = in[i];
    v.x = rnd_tf32(v.x); v.y = rnd_tf32(v.y);
    v.z = rnd_tf32(v.z); v.w = rnd_tf32(v.w);
    out[i] = v;
}

// in: [R,C] row-major per expert -> out: [C,R] row-major, tf32-rounded
__global__ void conv_t(const float* __restrict__ in, float* __restrict__ out,
                       int R, int C) {
    __shared__ float t[32][33];
    const size_t eo = (size_t)blockIdx.z * R * C;
    in += eo; out += eo;
    const int c0 = blockIdx.x * 32, r0 = blockIdx.y * 32;
    const int tx = threadIdx.x, ty = threadIdx.y;
#pragma unroll
    for (int j = 0; j < 32; j += 8)
        t[ty + j][tx] = rnd_tf32(in[(size_t)(r0 + ty + j) * C + c0 + tx]);
    __syncthreads();
#pragma unroll
    for (int j = 0; j < 32; j += 8)
        out[(size_t)(c0 + ty + j) * R + r0 + tx] = t[tx][ty + j];
}

// ---------------------------------------------------------------------------
// SwiGLU elementwise: hid = tf32_round( silu(t1) * t3 )
// ---------------------------------------------------------------------------
__global__ void swiglu_ew(const float4* __restrict__ t1,
                          const float4* __restrict__ t3,
                          float4* __restrict__ h, int n4) {
    int i = blockIdx.x * blockDim.x + threadIdx.x;
    if (i >= n4) return;
    float4 a = t1[i], b = t3[i], o;
    o.x = rnd_tf32(a.x / (1.0f + __expf(-a.x)) * b.x);
    o.y = rnd_tf32(a.y / (1.0f + __expf(-a.y)) * b.y);
    o.z = rnd_tf32(a.z / (1.0f + __expf(-a.z)) * b.z);
    o.w = rnd_tf32(a.w / (1.0f + __expf(-a.w)) * b.w);
    h[i] = o;
}

// ---------------------------------------------------------------------------
// TF32 GEMM: C[e] = A[e] (M x K row-major) * B[e]^T  with B stored [N,K]
//   grid (NM/BM, N/BN, NE) -- m fast for weight-slice L2 reuse
//   raw mma.m16n8k8 + ldmatrix; 3-stage cp.async; 2 CTAs/SM
// smem layout per tile: row r (0..127), 16B chunk c (0..7):
//   off = r*128 + ((c ^ (r & 7)) << 4)        (XOR swizzle, conflict-free)
// ---------------------------------------------------------------------------
__global__ void __launch_bounds__(NT, 2)
gemm_tf32(const float* __restrict__ Ag, const float* __restrict__ Bg,
          float* __restrict__ Cg, int N, int K) {
    extern __shared__ char smc[];
    const int e  = blockIdx.z;
    const int m0 = blockIdx.x * BM;
    const int n0 = blockIdx.y * BN;

    const float* A = Ag + (size_t)e * NM * K;
    const float* B = Bg + (size_t)e * (size_t)N * K;
    float*       C = Cg + (size_t)e * NM * N;

    const int tid  = threadIdx.x;
    const int warp = tid >> 5;
    const int l    = tid & 31;
    const int wm   = warp >> 1;      // 0..3 -> m rows wm*32
    const int wn   = warp & 1;       // 0..1 -> n cols wn*64
    const int lr7  = l & 7;

    const uint32_t smem0 = (uint32_t)__cvta_generic_to_shared(smc);

    // ldmatrix lane geometry
    // A (x4): mat0 rows 0-7 lo-16B, mat1 rows 8-15 lo, mat2 rows 0-7 hi, mat3 rows 8-15 hi
    const int a_row = wm * 32 + ((l >> 3) & 1) * 8 + lr7;    // + mt*16
    const int a_cb  = (l >> 4) & 1;
    // B (x4): mat0 n0-7 lo, mat1 n0-7 hi, mat2 n8-15 lo, mat3 n8-15 hi
    const int b_row = wn * 64 + ((l >> 4) & 1) * 8 + lr7;    // + nt*16
    const int b_cb  = (l >> 3) & 1;

    // cp.async fill geometry: 1024 16B-chunks per tile, 4 per thread
    const int f_row = tid >> 3;          // +32 per step
    const int f_c   = tid & 7;

    float acc[2][8][4];
#pragma unroll
    for (int i = 0; i < 2; i++)
#pragma unroll
        for (int j = 0; j < 8; j++)
#pragma unroll
            for (int t = 0; t < 4; t++) acc[i][j][t] = 0.0f;

    auto fill = [&](int st, int kt) {
        uint32_t sa = smem0 + st * STG_B;
        uint32_t sb = sa + TILE_B;
#pragma unroll
        for (int i = 0; i < 4; i++) {
            int row = f_row + i * 32;
            uint32_t off = row * 128 + ((f_c ^ (row & 7)) << 4);
            cp16(sa + off, A + (size_t)(m0 + row) * K + kt + f_c * 4);
            cp16(sb + off, B + (size_t)(n0 + row) * K + kt + f_c * 4);
        }
    };

    const int NIT = K / BK;
    fill(0, 0);  cp_commit();
    fill(1, BK); cp_commit();

    for (int it = 0; it < NIT; it++) {
        cp_wait<1>();
        __syncthreads();

        int nt = it + 2;
        if (nt < NIT) fill(nt % STAGES, nt * BK);
        cp_commit();

        uint32_t sa = smem0 + (it % STAGES) * STG_B;
        uint32_t sb = sa + TILE_B;

#pragma unroll
        for (int kk = 0; kk < 4; kk++) {
            // A fragments: 2 m16 tiles
            uint32_t a[2][4];
#pragma unroll
            for (int mt = 0; mt < 2; mt++) {
                int row = a_row + mt * 16;
                int ch  = 2 * kk + a_cb;
                ldm4(a[mt][0], a[mt][1], a[mt][2], a[mt][3],
                     sa + row * 128 + ((ch ^ lr7) << 4));
            }
            // B fragments: 4 n16 tiles (each x4 = two n8 frags)
            uint32_t b[4][4];
#pragma unroll
            for (int ntl = 0; ntl < 4; ntl++) {
                int row = b_row + ntl * 16;
                int ch  = 2 * kk + b_cb;
                ldm4(b[ntl][0], b[ntl][1], b[ntl][2], b[ntl][3],
                     sb + row * 128 + ((ch ^ lr7) << 4));
            }
#pragma unroll
            for (int mt = 0; mt < 2; mt++)
#pragma unroll
                for (int ntl = 0; ntl < 4; ntl++) {
                    mma_tf32(acc[mt][2 * ntl + 0],
                             a[mt][0], a[mt][1], a[mt][2], a[mt][3],
                             b[ntl][0], b[ntl][1]);
                    mma_tf32(acc[mt][2 * ntl + 1],
                             a[mt][0], a[mt][1], a[mt][2], a[mt][3],
                             b[ntl][2], b[ntl][3]);
                }
        }
    }

    // Epilogue: c0,c1 -> (row, col..col+1); c2,c3 -> (row+8, col..col+1)
    const int erow = m0 + wm * 32 + (l >> 2);
    const int ecol = n0 + wn * 64 + 2 * (l & 3);
#pragma unroll
    for (int mt = 0; mt < 2; mt++)
#pragma unroll
        for (int j = 0; j < 8; j++) {
            float* p0 = C + (size_t)(erow + mt * 16) * N + ecol + j * 8;
            float* p1 = p0 + 8 * N;
            *reinterpret_cast<float2*>(p0) =
                make_float2(acc[mt][j][0], acc[mt][j][1]);
            *reinterpret_cast<float2*>(p1) =
                make_float2(acc[mt][j][2], acc[mt][j][3]);
        }
}

// ---------------------------------------------------------------------------
// Launch
// ---------------------------------------------------------------------------
extern "C" void kernel_launch(void* const* d_in, const int* in_sizes, int n_in,
                              void* d_out, int out_size) {
    const float* x  = (const float*)d_in[0];   // (E, M, H)
    const float* w1 = (const float*)d_in[1];   // (E, H, F)
    const float* w2 = (const float*)d_in[2];   // (E, F, H)
    const float* w3 = (const float*)d_in[3];   // (E, H, F)
    float* out = (float*)d_out;                // (E, M, H)

    cudaFuncSetAttribute(gemm_tf32,
                         cudaFuncAttributeMaxDynamicSharedMemorySize, SMEM);

    void *pxc, *pw1, *pw2, *pw3, *pt1, *pt3, *ph;
    cudaGetSymbolAddress(&pxc, g_xc);
    cudaGetSymbolAddress(&pw1, g_w1t);
    cudaGetSymbolAddress(&pw2, g_w2t);
    cudaGetSymbolAddress(&pw3, g_w3t);
    cudaGetSymbolAddress(&pt1, g_t1);
    cudaGetSymbolAddress(&pt3, g_t3);
    cudaGetSymbolAddress(&ph,  g_hid);

    // x: elementwise tf32 round
    const int nx4 = NE * NM * NH / 4;
    conv_x<<<(nx4 + 255) / 256, 256>>>((const float4*)x, (float4*)pxc, nx4);

    // weights: tf32 round + transpose to [N,K]
    dim3 tb(32, 8);
    conv_t<<<dim3(NF / 32, NH / 32, NE), tb>>>(w1, (float*)pw1, NH, NF); // ->[F,H]
    conv_t<<<dim3(NF / 32, NH / 32, NE), tb>>>(w3, (float*)pw3, NH, NF); // ->[F,H]
    conv_t<<<dim3(NH / 32, NF / 32, NE), tb>>>(w2, (float*)pw2, NF, NH); // ->[H,F]

    // t1 = x*w1^T', t3 = x*w3^T'   (M=2048, N=7168, K=2048)
    dim3 g1(NM / BM, NF / BN, NE);   // 16 x 56 x 8
    gemm_tf32<<<g1, NT, SMEM>>>((const float*)pxc, (const float*)pw1,
                                (float*)pt1, NF, NH);
    gemm_tf32<<<g1, NT, SMEM>>>((const float*)pxc, (const float*)pw3,
                                (float*)pt3, NF, NH);

    // hid = tf32( silu(t1) * t3 )
    const int nh4 = NE * NM * NF / 4;
    swiglu_ew<<<(nh4 + 255) / 256, 256>>>((const float4*)pt1, (const float4*)pt3,
                                          (float4*)ph, nh4);

    // out = hid * w2^T'   (M=2048, N=2048, K=7168)
    dim3 g2(NM / BM, NH / BN, NE);   // 16 x 16 x 8
    gemm_tf32<<<g2, NT, SMEM>>>((const float*)ph, (const float*)pw2,
                                out, NH, NF);
}

// round 11
// speedup vs baseline: 3.4614x; 1.0593x over previous
#include <cuda_runtime.h>
#include <mma.h>
#include <cstdint>

namespace {
constexpr int NE = 8, NM = 2048, NH = 2048, NF = 7168;

constexpr int BM = 128, BK = 32;
constexpr int STAGES = 3;
constexpr int NT = 256;                    // 8 warps

// gemm2 (single-B): BN=128, warp tile 32x64
constexpr int BN2 = 128;
constexpr int TILE_A  = BM * BK * 4;           // 16384 B
constexpr int TILE_B2 = BN2 * BK * 4;          // 16384 B
constexpr int STG2_B  = TILE_A + TILE_B2;      // 32 KB
constexpr unsigned SMEM2 = STAGES * STG2_B;    // 96 KB

// fused dual gemm1 (B1+B3): BN=64, warp tile 32x32 per output
constexpr int BN1 = 64;
constexpr int TILE_B1 = BN1 * BK * 4;          // 8192 B
constexpr int STG1_B  = TILE_A + 2 * TILE_B1;  // 32 KB
constexpr unsigned SMEM1 = STAGES * STG1_B;    // 96 KB
}

// ---------------------------------------------------------------------------
// Static device scratch (no cudaMalloc allowed)
// ---------------------------------------------------------------------------
__device__ float g_xc [(size_t)NE * NM * NH];   // x  tf32-rounded   [M,K=H]
__device__ float g_w1t[(size_t)NE * NF * NH];   // w1^T tf32-rounded [N=F,K=H]
__device__ float g_w3t[(size_t)NE * NF * NH];   // w3^T tf32-rounded [N=F,K=H]
__device__ float g_w2t[(size_t)NE * NH * NF];   // w2^T tf32-rounded [N=H,K=F]
__device__ float g_hid[(size_t)NE * NM * NF];   // silu(xw1)*xw3, tf32-rounded

// ---------------------------------------------------------------------------
// helpers
// ---------------------------------------------------------------------------
__device__ __forceinline__ float rnd_tf32(float v) {
    return nvcuda::wmma::__float_to_tf32(v);   // cvt.rna.tf32.f32
}
__device__ __forceinline__ void cp16(uint32_t dst, const float* src) {
    asm volatile("cp.async.cg.shared.global [%0], [%1], 16;\n" :: "r"(dst), "l"(src));
}
__device__ __forceinline__ void cp_commit() {
    asm volatile("cp.async.commit_group;\n");
}
template <int N> __device__ __forceinline__ void cp_wait() {
    asm volatile("cp.async.wait_group %0;\n" :: "n"(N));
}
__device__ __forceinline__ void ldm4(uint32_t& r0, uint32_t& r1,
                                     uint32_t& r2, uint32_t& r3, uint32_t addr) {
    asm volatile("ldmatrix.sync.aligned.m8n8.x4.shared.b16 {%0,%1,%2,%3}, [%4];"
                 : "=r"(r0), "=r"(r1), "=r"(r2), "=r"(r3) : "r"(addr));
}
__device__ __forceinline__ void mma_tf32(float* c, const uint32_t* a,
                                         uint32_t b0, uint32_t b1) {
    asm volatile(
        "mma.sync.aligned.m16n8k8.row.col.f32.tf32.tf32.f32 "
        "{%0,%1,%2,%3}, {%4,%5,%6,%7}, {%8,%9}, {%0,%1,%2,%3};"
        : "+f"(c[0]), "+f"(c[1]), "+f"(c[2]), "+f"(c[3])
        : "r"(a[0]), "r"(a[1]), "r"(a[2]), "r"(a[3]), "r"(b0), "r"(b1));
}

// ---------------------------------------------------------------------------
// fp32 -> tf32 pre-round (elementwise) and round+transpose (weights -> [N,K])
// ---------------------------------------------------------------------------
__global__ void conv_x(const float4* __restrict__ in, float4* __restrict__ out,
                       int n4) {
    int i = blockIdx.x * blockDim.x + threadIdx.x;
    if (i >= n4) return;
    float4 v = in[i];
    v.x = rnd_tf32(v.x); v.y = rnd_tf32(v.y);
    v.z = rnd_tf32(v.z); v.w = rnd_tf32(v.w);
    out[i] = v;
}

__global__ void conv_t(const float* __restrict__ in, float* __restrict__ out,
                       int R, int C) {
    __shared__ float t[32][33];
    const size_t eo = (size_t)blockIdx.z * R * C;
    in += eo; out += eo;
    const int c0 = blockIdx.x * 32, r0 = blockIdx.y * 32;
    const int tx = threadIdx.x, ty = threadIdx.y;
#pragma unroll
    for (int j = 0; j < 32; j += 8)
        t[ty + j][tx] = rnd_tf32(in[(size_t)(r0 + ty + j) * C + c0 + tx]);
    __syncthreads();
#pragma unroll
    for (int j = 0; j < 32; j += 8)
        out[(size_t)(c0 + ty + j) * R + r0 + tx] = t[tx][ty + j];
}

// ---------------------------------------------------------------------------
// Fused dual GEMM1 + SwiGLU: hid = tf32( silu(x*w1^T) * (x*w3^T) )
//   A [M,K] row-major; B1,B3 [N,K] row-major. grid (NM/BM, NF/BN1, NE).
//   8 warps 4(m)x2(n); warp tile 32x32 per output; A smem shared.
// ---------------------------------------------------------------------------
__global__ void __launch_bounds__(NT, 2)
gemm1_swiglu(const float* __restrict__ Ag, const float* __restrict__ B1g,
             const float* __restrict__ B3g, float* __restrict__ Hg) {
    extern __shared__ char smc[];
    const int e  = blockIdx.z;
    const int m0 = blockIdx.x * BM;
    const int n0 = blockIdx.y * BN1;

    const float* A  = Ag  + (size_t)e * NM * NH;
    const float* B1 = B1g + (size_t)e * (size_t)NF * NH;
    const float* B3 = B3g + (size_t)e * (size_t)NF * NH;
    float*       H  = Hg  + (size_t)e * (size_t)NM * NF;

    const int tid  = threadIdx.x;
    const int warp = tid >> 5;
    const int l    = tid & 31;
    const int wm   = warp >> 1;      // 0..3 -> m rows wm*32
    const int wn   = warp & 1;       // 0..1 -> n cols wn*32
    const int lr7  = l & 7;

    const uint32_t smem0 = (uint32_t)__cvta_generic_to_shared(smc);

    const int a_row = wm * 32 + ((l >> 3) & 1) * 8 + lr7;  // + mt*16
    const int b_row = wn * 32 + ((l >> 4) & 1) * 8 + lr7;  // + ntl*16
    const int a_cb  = (l >> 4) & 1;
    const int b_cb  = (l >> 3) & 1;

    const int f_row = tid >> 3;      // A: +32/step, B: +32/step
    const int f_c   = tid & 7;

    float ac1[2][4][4], ac3[2][4][4];
#pragma unroll
    for (int i = 0; i < 2; i++)
#pragma unroll
        for (int j = 0; j < 4; j++)
#pragma unroll
            for (int t = 0; t < 4; t++) { ac1[i][j][t] = 0.f; ac3[i][j][t] = 0.f; }

    auto fill = [&](int st, int kt) {
        uint32_t sa  = smem0 + st * STG1_B;
        uint32_t sb1 = sa + TILE_A;
        uint32_t sb3 = sb1 + TILE_B1;
#pragma unroll
        for (int i = 0; i < 4; i++) {
            int row = f_row + i * 32;
            uint32_t off = row * 128 + ((f_c ^ (row & 7)) << 4);
            cp16(sa + off, A + (size_t)(m0 + row) * NH + kt + f_c * 4);
        }
#pragma unroll
        for (int i = 0; i < 2; i++) {
            int row = f_row + i * 32;
            uint32_t off = row * 128 + ((f_c ^ (row & 7)) << 4);
            size_t g = (size_t)(n0 + row) * NH + kt + f_c * 4;
            cp16(sb1 + off, B1 + g);
            cp16(sb3 + off, B3 + g);
        }
    };

    const int NIT = NH / BK;   // 64
    fill(0, 0);  cp_commit();
    fill(1, BK); cp_commit();

    for (int it = 0; it < NIT; it++) {
        cp_wait<1>();
        __syncthreads();

        int nt = it + 2;
        if (nt < NIT) fill(nt % STAGES, nt * BK);
        cp_commit();

        uint32_t sa  = smem0 + (it % STAGES) * STG1_B;
        uint32_t sb1 = sa + TILE_A;
        uint32_t sb3 = sb1 + TILE_B1;

#pragma unroll
        for (int kk = 0; kk < 4; kk++) {
            uint32_t a[2][4], b1[2][4], b3[2][4];
#pragma unroll
            for (int mt = 0; mt < 2; mt++) {
                int row = a_row + mt * 16;
                int ch  = 2 * kk + a_cb;
                ldm4(a[mt][0], a[mt][1], a[mt][2], a[mt][3],
                     sa + row * 128 + ((ch ^ lr7) << 4));
            }
#pragma unroll
            for (int ntl = 0; ntl < 2; ntl++) {
                int row = b_row + ntl * 16;
                int ch  = 2 * kk + b_cb;
                uint32_t so = row * 128 + ((ch ^ lr7) << 4);
                ldm4(b1[ntl][0], b1[ntl][1], b1[ntl][2], b1[ntl][3], sb1 + so);
                ldm4(b3[ntl][0], b3[ntl][1], b3[ntl][2], b3[ntl][3], sb3 + so);
            }
#pragma unroll
            for (int mt = 0; mt < 2; mt++)
#pragma unroll
                for (int ntl = 0; ntl < 2; ntl++) {
                    mma_tf32(ac1[mt][2 * ntl + 0], a[mt], b1[ntl][0], b1[ntl][1]);
                    mma_tf32(ac1[mt][2 * ntl + 1], a[mt], b1[ntl][2], b1[ntl][3]);
                    mma_tf32(ac3[mt][2 * ntl + 0], a[mt], b3[ntl][0], b3[ntl][1]);
                    mma_tf32(ac3[mt][2 * ntl + 1], a[mt], b3[ntl][2], b3[ntl][3]);
                }
        }
    }

    // SwiGLU epilogue, elementwise on identical fragment mappings.
    const int erow = m0 + wm * 32 + (l >> 2);
    const int ecol = n0 + wn * 32 + 2 * (l & 3);
#pragma unroll
    for (int mt = 0; mt < 2; mt++)
#pragma unroll
        for (int j = 0; j < 4; j++) {
            float v0 = ac1[mt][j][0], v1 = ac1[mt][j][1];
            float v2 = ac1[mt][j][2], v3 = ac1[mt][j][3];
            float h0 = rnd_tf32(v0 / (1.0f + __expf(-v0)) * ac3[mt][j][0]);
            float h1 = rnd_tf32(v1 / (1.0f + __expf(-v1)) * ac3[mt][j][1]);
            float h2 = rnd_tf32(v2 / (1.0f + __expf(-v2)) * ac3[mt][j][2]);
            float h3 = rnd_tf32(v3 / (1.0f + __expf(-v3)) * ac3[mt][j][3]);
            float* p0 = H + (size_t)(erow + mt * 16) * NF + ecol + j * 8;
            *reinterpret_cast<float2*>(p0)          = make_float2(h0, h1);
            *reinterpret_cast<float2*>(p0 + 8 * NF) = make_float2(h2, h3);
        }
}

// ---------------------------------------------------------------------------
// GEMM2: out = hid * w2^T   A [M,K=F], B [N=H,K=F]. grid (NM/BM, NH/BN2, NE)
// ---------------------------------------------------------------------------
__global__ void __launch_bounds__(NT, 2)
gemm_tf32(const float* __restrict__ Ag, const float* __restrict__ Bg,
          float* __restrict__ Cg, int N, int K) {
    extern __shared__ char smc[];
    const int e  = blockIdx.z;
    const int m0 = blockIdx.x * BM;
    const int n0 = blockIdx.y * BN2;

    const float* A = Ag + (size_t)e * NM * K;
    const float* B = Bg + (size_t)e * (size_t)N * K;
    float*       C = Cg + (size_t)e * NM * N;

    const int tid  = threadIdx.x;
    const int warp = tid >> 5;
    const int l    = tid & 31;
    const int wm   = warp >> 1;
    const int wn   = warp & 1;       // cols wn*64
    const int lr7  = l & 7;

    const uint32_t smem0 = (uint32_t)__cvta_generic_to_shared(smc);

    const int a_row = wm * 32 + ((l >> 3) & 1) * 8 + lr7;
    const int a_cb  = (l >> 4) & 1;
    const int b_row = wn * 64 + ((l >> 4) & 1) * 8 + lr7;
    const int b_cb  = (l >> 3) & 1;

    const int f_row = tid >> 3;
    const int f_c   = tid & 7;

    float acc[2][8][4];
#pragma unroll
    for (int i = 0; i < 2; i++)
#pragma unroll
        for (int j = 0; j < 8; j++)
#pragma unroll
            for (int t = 0; t < 4; t++) acc[i][j][t] = 0.0f;

    auto fill = [&](int st, int kt) {
        uint32_t sa = smem0 + st * STG2_B;
        uint32_t sb = sa + TILE_A;
#pragma unroll
        for (int i = 0; i < 4; i++) {
            int row = f_row + i * 32;
            uint32_t off = row * 128 + ((f_c ^ (row & 7)) << 4);
            cp16(sa + off, A + (size_t)(m0 + row) * K + kt + f_c * 4);
            cp16(sb + off, B + (size_t)(n0 + row) * K + kt + f_c * 4);
        }
    };

    const int NIT = K / BK;
    fill(0, 0);  cp_commit();
    fill(1, BK); cp_commit();

    for (int it = 0; it < NIT; it++) {
        cp_wait<1>();
        __syncthreads();

        int nt = it + 2;
        if (nt < NIT) fill(nt % STAGES, nt * BK);
        cp_commit();

        uint32_t sa = smem0 + (it % STAGES) * STG2_B;
        uint32_t sb = sa + TILE_A;

#pragma unroll
        for (int kk = 0; kk < 4; kk++) {
            uint32_t a[2][4], b[4][4];
#pragma unroll
            for (int mt = 0; mt < 2; mt++) {
                int row = a_row + mt * 16;
                int ch  = 2 * kk + a_cb;
                ldm4(a[mt][0], a[mt][1], a[mt][2], a[mt][3],
                     sa + row * 128 + ((ch ^ lr7) << 4));
            }
#pragma unroll
            for (int ntl = 0; ntl < 4; ntl++) {
                int row = b_row + ntl * 16;
                int ch  = 2 * kk + b_cb;
                ldm4(b[ntl][0], b[ntl][1], b[ntl][2], b[ntl][3],
                     sb + row * 128 + ((ch ^ lr7) << 4));
            }
#pragma unroll
            for (int mt = 0; mt < 2; mt++)
#pragma unroll
                for (int ntl = 0; ntl < 4; ntl++) {
                    mma_tf32(acc[mt][2 * ntl + 0], a[mt], b[ntl][0], b[ntl][1]);
                    mma_tf32(acc[mt][2 * ntl + 1], a[mt], b[ntl][2], b[ntl][3]);
                }
        }
    }

    const int erow = m0 + wm * 32 + (l >> 2);
    const int ecol = n0 + wn * 64 + 2 * (l & 3);
#pragma unroll
    for (int mt = 0; mt < 2; mt++)
#pragma unroll
        for (int j = 0; j < 8; j++) {
            float* p0 = C + (size_t)(erow + mt * 16) * N + ecol + j * 8;
            *reinterpret_cast<float2*>(p0)         = make_float2(acc[mt][j][0], acc[mt][j][1]);
            *reinterpret_cast<float2*>(p0 + 8 * N) = make_float2(acc[mt][j][2], acc[mt][j][3]);
        }
}

// ---------------------------------------------------------------------------
// Launch
// ---------------------------------------------------------------------------
extern "C" void kernel_launch(void* const* d_in, const int* in_sizes, int n_in,
                              void* d_out, int out_size) {
    const float* x  = (const float*)d_in[0];   // (E, M, H)
    const float* w1 = (const float*)d_in[1];   // (E, H, F)
    const float* w2 = (const float*)d_in[2];   // (E, F, H)
    const float* w3 = (const float*)d_in[3];   // (E, H, F)
    float* out = (float*)d_out;                // (E, M, H)

    cudaFuncSetAttribute(gemm1_swiglu,
                         cudaFuncAttributeMaxDynamicSharedMemorySize, SMEM1);
    cudaFuncSetAttribute(gemm_tf32,
                         cudaFuncAttributeMaxDynamicSharedMemorySize, SMEM2);

    void *pxc, *pw1, *pw2, *pw3, *ph;
    cudaGetSymbolAddress(&pxc, g_xc);
    cudaGetSymbolAddress(&pw1, g_w1t);
    cudaGetSymbolAddress(&pw2, g_w2t);
    cudaGetSymbolAddress(&pw3, g_w3t);
    cudaGetSymbolAddress(&ph,  g_hid);

    const int nx4 = NE * NM * NH / 4;
    conv_x<<<(nx4 + 255) / 256, 256>>>((const float4*)x, (float4*)pxc, nx4);

    dim3 tb(32, 8);
    conv_t<<<dim3(NF / 32, NH / 32, NE), tb>>>(w1, (float*)pw1, NH, NF); // ->[F,H]
    conv_t<<<dim3(NF / 32, NH / 32, NE), tb>>>(w3, (float*)pw3, NH, NF); // ->[F,H]
    conv_t<<<dim3(NH / 32, NF / 32, NE), tb>>>(w2, (float*)pw2, NF, NH); // ->[H,F]

    // fused: hid = tf32( silu(x*w1^T) * (x*w3^T) )
    dim3 g1(NM / BM, NF / BN1, NE);   // 16 x 112 x 8
    gemm1_swiglu<<<g1, NT, SMEM1>>>((const float*)pxc, (const float*)pw1,
                                    (const float*)pw3, (float*)ph);

    // out = hid * w2^T
    dim3 g2(NM / BM, NH / BN2, NE);   // 16 x 16 x 8
    gemm_tf32<<<g2, NT, SMEM2>>>((const float*)ph, (const float*)pw2,
                                 out, NH, NF);
}

// round 12
// speedup vs baseline: 6.4931x; 1.8758x over previous
#include <cuda_runtime.h>
#include <cuda_fp16.h>
#include <cstdint>

namespace {
constexpr int NE = 8, NM = 2048, NH = 2048, NF = 7168;

constexpr int BM = 128, BK = 64;           // 64 fp16 = 128B rows
constexpr int STAGES = 3;
constexpr int NT = 256;                    // 8 warps

// gemm2 (single-B): BN=128, warp tile 32x64
constexpr int BN2 = 128;
constexpr int TILE_A  = BM * BK * 2;           // 16384 B
constexpr int TILE_B2 = BN2 * BK * 2;          // 16384 B
constexpr int STG2_B  = TILE_A + TILE_B2;      // 32 KB
constexpr unsigned SMEM2 = STAGES * STG2_B;    // 96 KB

// fused dual gemm1 (B1+B3): BN=64, warp tile 32x32 per output
constexpr int BN1 = 64;
constexpr int TILE_B1 = BN1 * BK * 2;          // 8192 B
constexpr int STG1_B  = TILE_A + 2 * TILE_B1;  // 32 KB
constexpr unsigned SMEM1 = STAGES * STG1_B;    // 96 KB
}

// ---------------------------------------------------------------------------
// Static device scratch (no cudaMalloc allowed)
// ---------------------------------------------------------------------------
__device__ __half g_xc [(size_t)NE * NM * NH];   // x  fp16           [M,K=H]
__device__ __half g_w1t[(size_t)NE * NF * NH];   // w1^T fp16         [N=F,K=H]
__device__ __half g_w3t[(size_t)NE * NF * NH];   // w3^T fp16         [N=F,K=H]
__device__ __half g_w2t[(size_t)NE * NH * NF];   // w2^T fp16         [N=H,K=F]
__device__ __half g_hid[(size_t)NE * NM * NF];   // silu(xw1)*xw3 fp16[M,K=F]

// ---------------------------------------------------------------------------
// helpers
// ---------------------------------------------------------------------------
__device__ __forceinline__ void cp16(uint32_t dst, const void* src) {
    asm volatile("cp.async.cg.shared.global [%0], [%1], 16;\n" :: "r"(dst), "l"(src));
}
__device__ __forceinline__ void cp_commit() {
    asm volatile("cp.async.commit_group;\n");
}
template <int N> __device__ __forceinline__ void cp_wait() {
    asm volatile("cp.async.wait_group %0;\n" :: "n"(N));
}
__device__ __forceinline__ void ldm4(uint32_t& r0, uint32_t& r1,
                                     uint32_t& r2, uint32_t& r3, uint32_t addr) {
    asm volatile("ldmatrix.sync.aligned.m8n8.x4.shared.b16 {%0,%1,%2,%3}, [%4];"
                 : "=r"(r0), "=r"(r1), "=r"(r2), "=r"(r3) : "r"(addr));
}
__device__ __forceinline__ void mma_f16(float* c, const uint32_t* a,
                                        uint32_t b0, uint32_t b1) {
    asm volatile(
        "mma.sync.aligned.m16n8k16.row.col.f32.f16.f16.f32 "
        "{%0,%1,%2,%3}, {%4,%5,%6,%7}, {%8,%9}, {%0,%1,%2,%3};"
        : "+f"(c[0]), "+f"(c[1]), "+f"(c[2]), "+f"(c[3])
        : "r"(a[0]), "r"(a[1]), "r"(a[2]), "r"(a[3]), "r"(b0), "r"(b1));
}

// ---------------------------------------------------------------------------
// fp32 -> fp16 pre-round (elementwise) and round+transpose (weights -> [N,K])
// ---------------------------------------------------------------------------
__global__ void conv_x(const float4* __restrict__ in, __half2* __restrict__ out,
                       int n4) {
    int i = blockIdx.x * blockDim.x + threadIdx.x;
    if (i >= n4) return;
    float4 v = in[i];
    out[2 * i + 0] = __floats2half2_rn(v.x, v.y);
    out[2 * i + 1] = __floats2half2_rn(v.z, v.w);
}

// in: [R,C] fp32 row-major per expert -> out: [C,R] fp16 row-major
__global__ void conv_t(const float* __restrict__ in, __half* __restrict__ out,
                       int R, int C) {
    __shared__ float t[32][33];
    in  += (size_t)blockIdx.z * R * C;
    out += (size_t)blockIdx.z * R * C;
    const int c0 = blockIdx.x * 32, r0 = blockIdx.y * 32;
    const int tx = threadIdx.x, ty = threadIdx.y;
#pragma unroll
    for (int j = 0; j < 32; j += 8)
        t[ty + j][tx] = in[(size_t)(r0 + ty + j) * C + c0 + tx];
    __syncthreads();
#pragma unroll
    for (int j = 0; j < 32; j += 8)
        out[(size_t)(c0 + ty + j) * R + r0 + tx] = __float2half_rn(t[tx][ty + j]);
}

// ---------------------------------------------------------------------------
// Fused dual GEMM1 + SwiGLU: hid = fp16( silu(x*w1^T) * (x*w3^T) )
//   A [M,K] row-major fp16; B1,B3 [N,K] row-major fp16.
//   grid (NM/BM, NF/BN1, NE); 8 warps 4(m)x2(n); warp tile 32x32 per output.
// smem tile: row r, 16B chunk c (0..7; chunk c = k c*8..c*8+7):
//   off = r*128 + ((c ^ (r & 7)) << 4)
// ---------------------------------------------------------------------------
__global__ void __launch_bounds__(NT, 2)
gemm1_swiglu(const __half* __restrict__ Ag, const __half* __restrict__ B1g,
             const __half* __restrict__ B3g, __half* __restrict__ Hg) {
    extern __shared__ char smc[];
    const int e  = blockIdx.z;
    const int m0 = blockIdx.x * BM;
    const int n0 = blockIdx.y * BN1;

    const __half* A  = Ag  + (size_t)e * NM * NH;
    const __half* B1 = B1g + (size_t)e * (size_t)NF * NH;
    const __half* B3 = B3g + (size_t)e * (size_t)NF * NH;
    __half*       H  = Hg  + (size_t)e * (size_t)NM * NF;

    const int tid  = threadIdx.x;
    const int warp = tid >> 5;
    const int l    = tid & 31;
    const int wm   = warp >> 1;      // m rows wm*32
    const int wn   = warp & 1;       // n cols wn*32
    const int lr7  = l & 7;

    const uint32_t smem0 = (uint32_t)__cvta_generic_to_shared(smc);

    // ldmatrix x4 lane geometry (b16 8x8 tiles)
    const int a_row = wm * 32 + ((l >> 3) & 1) * 8 + lr7;  // + mt*16
    const int a_cb  = (l >> 4) & 1;                         // lo/hi k8 chunk
    const int b_row = wn * 32 + ((l >> 4) & 1) * 8 + lr7;  // + ntl*16
    const int b_cb  = (l >> 3) & 1;

    const int f_row = tid >> 3;      // fill: +32 rows/step
    const int f_c   = tid & 7;

    float ac1[2][4][4], ac3[2][4][4];
#pragma unroll
    for (int i = 0; i < 2; i++)
#pragma unroll
        for (int j = 0; j < 4; j++)
#pragma unroll
            for (int t = 0; t < 4; t++) { ac1[i][j][t] = 0.f; ac3[i][j][t] = 0.f; }

    auto fill = [&](int st, int kt) {
        uint32_t sa  = smem0 + st * STG1_B;
        uint32_t sb1 = sa + TILE_A;
        uint32_t sb3 = sb1 + TILE_B1;
#pragma unroll
        for (int i = 0; i < 4; i++) {
            int row = f_row + i * 32;
            uint32_t off = row * 128 + ((f_c ^ (row & 7)) << 4);
            cp16(sa + off, A + (size_t)(m0 + row) * NH + kt + f_c * 8);
        }
#pragma unroll
        for (int i = 0; i < 2; i++) {
            int row = f_row + i * 32;
            uint32_t off = row * 128 + ((f_c ^ (row & 7)) << 4);
            size_t g = (size_t)(n0 + row) * NH + kt + f_c * 8;
            cp16(sb1 + off, B1 + g);
            cp16(sb3 + off, B3 + g);
        }
    };

    const int NIT = NH / BK;   // 32
    fill(0, 0);  cp_commit();
    fill(1, BK); cp_commit();

    for (int it = 0; it < NIT; it++) {
        cp_wait<1>();
        __syncthreads();

        int nt = it + 2;
        if (nt < NIT) fill(nt % STAGES, nt * BK);
        cp_commit();

        uint32_t sa  = smem0 + (it % STAGES) * STG1_B;
        uint32_t sb1 = sa + TILE_A;
        uint32_t sb3 = sb1 + TILE_B1;

#pragma unroll
        for (int kk = 0; kk < 4; kk++) {        // k16 steps
            uint32_t a[2][4], b1[2][4], b3[2][4];
#pragma unroll
            for (int mt = 0; mt < 2; mt++) {
                int row = a_row + mt * 16;
                int ch  = 2 * kk + a_cb;
                ldm4(a[mt][0], a[mt][1], a[mt][2], a[mt][3],
                     sa + row * 128 + ((ch ^ lr7) << 4));
            }
#pragma unroll
            for (int ntl = 0; ntl < 2; ntl++) {
                int row = b_row + ntl * 16;
                int ch  = 2 * kk + b_cb;
                uint32_t so = row * 128 + ((ch ^ lr7) << 4);
                ldm4(b1[ntl][0], b1[ntl][1], b1[ntl][2], b1[ntl][3], sb1 + so);
                ldm4(b3[ntl][0], b3[ntl][1], b3[ntl][2], b3[ntl][3], sb3 + so);
            }
#pragma unroll
            for (int mt = 0; mt < 2; mt++)
#pragma unroll
                for (int ntl = 0; ntl < 2; ntl++) {
                    mma_f16(ac1[mt][2 * ntl + 0], a[mt], b1[ntl][0], b1[ntl][1]);
                    mma_f16(ac1[mt][2 * ntl + 1], a[mt], b1[ntl][2], b1[ntl][3]);
                    mma_f16(ac3[mt][2 * ntl + 0], a[mt], b3[ntl][0], b3[ntl][1]);
                    mma_f16(ac3[mt][2 * ntl + 1], a[mt], b3[ntl][2], b3[ntl][3]);
                }
        }
    }

    // SwiGLU epilogue (identical fragment mappings), store fp16 hidden.
    const int erow = m0 + wm * 32 + (l >> 2);
    const int ecol = n0 + wn * 32 + 2 * (l & 3);
#pragma unroll
    for (int mt = 0; mt < 2; mt++)
#pragma unroll
        for (int j = 0; j < 4; j++) {
            float v0 = ac1[mt][j][0], v1 = ac1[mt][j][1];
            float v2 = ac1[mt][j][2], v3 = ac1[mt][j][3];
            float h0 = v0 / (1.0f + __expf(-v0)) * ac3[mt][j][0];
            float h1 = v1 / (1.0f + __expf(-v1)) * ac3[mt][j][1];
            float h2 = v2 / (1.0f + __expf(-v2)) * ac3[mt][j][2];
            float h3 = v3 / (1.0f + __expf(-v3)) * ac3[mt][j][3];
            __half* p0 = H + (size_t)(erow + mt * 16) * NF + ecol + j * 8;
            *reinterpret_cast<__half2*>(p0)          = __floats2half2_rn(h0, h1);
            *reinterpret_cast<__half2*>(p0 + 8 * NF) = __floats2half2_rn(h2, h3);
        }
}

// ---------------------------------------------------------------------------
// GEMM2: out = hid * w2^T   A [M,K=F] fp16, B [N=H,K=F] fp16, C fp32.
//   grid (NM/BM, NH/BN2, NE); warp tile 32x64.
// ---------------------------------------------------------------------------
__global__ void __launch_bounds__(NT, 2)
gemm_f16(const __half* __restrict__ Ag, const __half* __restrict__ Bg,
         float* __restrict__ Cg, int N, int K) {
    extern __shared__ char smc[];
    const int e  = blockIdx.z;
    const int m0 = blockIdx.x * BM;
    const int n0 = blockIdx.y * BN2;

    const __half* A = Ag + (size_t)e * NM * K;
    const __half* B = Bg + (size_t)e * (size_t)N * K;
    float*        C = Cg + (size_t)e * NM * N;

    const int tid  = threadIdx.x;
    const int warp = tid >> 5;
    const int l    = tid & 31;
    const int wm   = warp >> 1;
    const int wn   = warp & 1;       // cols wn*64
    const int lr7  = l & 7;

    const uint32_t smem0 = (uint32_t)__cvta_generic_to_shared(smc);

    const int a_row = wm * 32 + ((l >> 3) & 1) * 8 + lr7;
    const int a_cb  = (l >> 4) & 1;
    const int b_row = wn * 64 + ((l >> 4) & 1) * 8 + lr7;
    const int b_cb  = (l >> 3) & 1;

    const int f_row = tid >> 3;
    const int f_c   = tid & 7;

    float acc[2][8][4];
#pragma unroll
    for (int i = 0; i < 2; i++)
#pragma unroll
        for (int j = 0; j < 8; j++)
#pragma unroll
            for (int t = 0; t < 4; t++) acc[i][j][t] = 0.0f;

    auto fill = [&](int st, int kt) {
        uint32_t sa = smem0 + st * STG2_B;
        uint32_t sb = sa + TILE_A;
#pragma unroll
        for (int i = 0; i < 4; i++) {
            int row = f_row + i * 32;
            uint32_t off = row * 128 + ((f_c ^ (row & 7)) << 4);
            cp16(sa + off, A + (size_t)(m0 + row) * K + kt + f_c * 8);
            cp16(sb + off, B + (size_t)(n0 + row) * K + kt + f_c * 8);
        }
    };

    const int NIT = K / BK;   // 112
    fill(0, 0);  cp_commit();
    fill(1, BK); cp_commit();

    for (int it = 0; it < NIT; it++) {
        cp_wait<1>();
        __syncthreads();

        int nt = it + 2;
        if (nt < NIT) fill(nt % STAGES, nt * BK);
        cp_commit();

        uint32_t sa = smem0 + (it % STAGES) * STG2_B;
        uint32_t sb = sa + TILE_A;

#pragma unroll
        for (int kk = 0; kk < 4; kk++) {
            uint32_t a[2][4], b[4][4];
#pragma unroll
            for (int mt = 0; mt < 2; mt++) {
                int row = a_row + mt * 16;
                int ch  = 2 * kk + a_cb;
                ldm4(a[mt][0], a[mt][1], a[mt][2], a[mt][3],
                     sa + row * 128 + ((ch ^ lr7) << 4));
            }
#pragma unroll
            for (int ntl = 0; ntl < 4; ntl++) {
                int row = b_row + ntl * 16;
                int ch  = 2 * kk + b_cb;
                ldm4(b[ntl][0], b[ntl][1], b[ntl][2], b[ntl][3],
                     sb + row * 128 + ((ch ^ lr7) << 4));
            }
#pragma unroll
            for (int mt = 0; mt < 2; mt++)
#pragma unroll
                for (int ntl = 0; ntl < 4; ntl++) {
                    mma_f16(acc[mt][2 * ntl + 0], a[mt], b[ntl][0], b[ntl][1]);
                    mma_f16(acc[mt][2 * ntl + 1], a[mt], b[ntl][2], b[ntl][3]);
                }
        }
    }

    const int erow = m0 + wm * 32 + (l >> 2);
    const int ecol = n0 + wn * 64 + 2 * (l & 3);
#pragma unroll
    for (int mt = 0; mt < 2; mt++)
#pragma unroll
        for (int j = 0; j < 8; j++) {
            float* p0 = C + (size_t)(erow + mt * 16) * N + ecol + j * 8;
            *reinterpret_cast<float2*>(p0)         = make_float2(acc[mt][j][0], acc[mt][j][1]);
            *reinterpret_cast<float2*>(p0 + 8 * N) = make_float2(acc[mt][j][2], acc[mt][j][3]);
        }
}

// ---------------------------------------------------------------------------
// Launch
// ---------------------------------------------------------------------------
extern "C" void kernel_launch(void* const* d_in, const int* in_sizes, int n_in,
                              void* d_out, int out_size) {
    const float* x  = (const float*)d_in[0];   // (E, M, H)
    const float* w1 = (const float*)d_in[1];   // (E, H, F)
    const float* w2 = (const float*)d_in[2];   // (E, F, H)
    const float* w3 = (const float*)d_in[3];   // (E, H, F)
    float* out = (float*)d_out;                // (E, M, H)

    cudaFuncSetAttribute(gemm1_swiglu,
                         cudaFuncAttributeMaxDynamicSharedMemorySize, SMEM1);
    cudaFuncSetAttribute(gemm_f16,
                         cudaFuncAttributeMaxDynamicSharedMemorySize, SMEM2);

    void *pxc, *pw1, *pw2, *pw3, *ph;
    cudaGetSymbolAddress(&pxc, g_xc);
    cudaGetSymbolAddress(&pw1, g_w1t);
    cudaGetSymbolAddress(&pw2, g_w2t);
    cudaGetSymbolAddress(&pw3, g_w3t);
    cudaGetSymbolAddress(&ph,  g_hid);

    const int nx4 = NE * NM * NH / 4;
    conv_x<<<(nx4 + 255) / 256, 256>>>((const float4*)x, (__half2*)pxc, nx4);

    dim3 tb(32, 8);
    conv_t<<<dim3(NF / 32, NH / 32, NE), tb>>>(w1, (__half*)pw1, NH, NF); // ->[F,H]
    conv_t<<<dim3(NF / 32, NH / 32, NE), tb>>>(w3, (__half*)pw3, NH, NF); // ->[F,H]
    conv_t<<<dim3(NH / 32, NF / 32, NE), tb>>>(w2, (__half*)pw2, NF, NH); // ->[H,F]

    // fused: hid = fp16( silu(x*w1^T) * (x*w3^T) )
    dim3 g1(NM / BM, NF / BN1, NE);   // 16 x 112 x 8
    gemm1_swiglu<<<g1, NT, SMEM1>>>((const __half*)pxc, (const __half*)pw1,
                                    (const __half*)pw3, (__half*)ph);

    // out = hid * w2^T
    dim3 g2(NM / BM, NH / BN2, NE);   // 16 x 16 x 8
    gemm_f16<<<g2, NT, SMEM2>>>((const __half*)ph, (const __half*)pw2,
                                out, NH, NF);
}

// round 13
// speedup vs baseline: 6.5085x; 1.0024x over previous
#include <cuda_runtime.h>
#include <cuda_fp16.h>
#include <cstdint>

namespace {
constexpr int NE = 8, NM = 2048, NH = 2048, NF = 7168;

constexpr int BM = 128, BK = 64;           // 64 fp16 = 128B rows
constexpr int STAGES = 3;
constexpr int NT = 256;                    // 8 warps

// gemm2 (single-B): BN=128, warp tile 32x64
constexpr int BN2 = 128;
constexpr int TILE_A  = BM * BK * 2;           // 16384 B
constexpr int TILE_B2 = BN2 * BK * 2;          // 16384 B
constexpr int STG2_B  = TILE_A + TILE_B2;      // 32 KB
constexpr unsigned SMEM2 = STAGES * STG2_B;    // 96 KB

// fused dual gemm1 (B1+B3): BN=64, warp tile 32x32 per output
constexpr int BN1 = 64;
constexpr int TILE_B1 = BN1 * BK * 2;          // 8192 B
constexpr int STG1_B  = TILE_A + 2 * TILE_B1;  // 32 KB
constexpr unsigned SMEM1 = STAGES * STG1_B;    // 96 KB
}

// ---------------------------------------------------------------------------
// Static device scratch (no cudaMalloc allowed)
// ---------------------------------------------------------------------------
__device__ __half g_xc [(size_t)NE * NM * NH];   // x  fp16           [M,K=H]
__device__ __half g_w1t[(size_t)NE * NF * NH];   // w1^T fp16         [N=F,K=H]
__device__ __half g_w3t[(size_t)NE * NF * NH];   // w3^T fp16         [N=F,K=H]
__device__ __half g_w2t[(size_t)NE * NH * NF];   // w2^T fp16         [N=H,K=F]
__device__ __half g_hid[(size_t)NE * NM * NF];   // silu(xw1)*xw3 fp16[M,K=F]

// ---------------------------------------------------------------------------
// helpers
// ---------------------------------------------------------------------------
__device__ __forceinline__ void cp16(uint32_t dst, const void* src) {
    asm volatile("cp.async.cg.shared.global [%0], [%1], 16;\n" :: "r"(dst), "l"(src));
}
__device__ __forceinline__ void cp_commit() {
    asm volatile("cp.async.commit_group;\n");
}
template <int N> __device__ __forceinline__ void cp_wait() {
    asm volatile("cp.async.wait_group %0;\n" :: "n"(N));
}
__device__ __forceinline__ void ldm4(uint32_t& r0, uint32_t& r1,
                                     uint32_t& r2, uint32_t& r3, uint32_t addr) {
    asm volatile("ldmatrix.sync.aligned.m8n8.x4.shared.b16 {%0,%1,%2,%3}, [%4];"
                 : "=r"(r0), "=r"(r1), "=r"(r2), "=r"(r3) : "r"(addr));
}
__device__ __forceinline__ void mma_f16(float* c, const uint32_t* a,
                                        uint32_t b0, uint32_t b1) {
    asm volatile(
        "mma.sync.aligned.m16n8k16.row.col.f32.f16.f16.f32 "
        "{%0,%1,%2,%3}, {%4,%5,%6,%7}, {%8,%9}, {%0,%1,%2,%3};"
        : "+f"(c[0]), "+f"(c[1]), "+f"(c[2]), "+f"(c[3])
        : "r"(a[0]), "r"(a[1]), "r"(a[2]), "r"(a[3]), "r"(b0), "r"(b1));
}

// ---------------------------------------------------------------------------
// fp32 -> fp16 pre-round (elementwise) and round+transpose (weights -> [N,K])
// ---------------------------------------------------------------------------
__global__ void conv_x(const float4* __restrict__ in, __half2* __restrict__ out,
                       int n4) {
    int i = blockIdx.x * blockDim.x + threadIdx.x;
    if (i >= n4) return;
    float4 v = in[i];
    out[2 * i + 0] = __floats2half2_rn(v.x, v.y);
    out[2 * i + 1] = __floats2half2_rn(v.z, v.w);
}

// in: [R,C] fp32 row-major per expert -> out: [C,R] fp16 row-major
__global__ void conv_t(const float* __restrict__ in, __half* __restrict__ out,
                       int R, int C) {
    __shared__ float t[32][33];
    in  += (size_t)blockIdx.z * R * C;
    out += (size_t)blockIdx.z * R * C;
    const int c0 = blockIdx.x * 32, r0 = blockIdx.y * 32;
    const int tx = threadIdx.x, ty = threadIdx.y;
#pragma unroll
    for (int j = 0; j < 32; j += 8)
        t[ty + j][tx] = in[(size_t)(r0 + ty + j) * C + c0 + tx];
    __syncthreads();
#pragma unroll
    for (int j = 0; j < 32; j += 8)
        out[(size_t)(c0 + ty + j) * R + r0 + tx] = __float2half_rn(t[tx][ty + j]);
}

// ---------------------------------------------------------------------------
// Fused dual GEMM1 + SwiGLU: hid = fp16( silu(x*w1^T) * (x*w3^T) )
//   A [M,K] row-major fp16; B1,B3 [N,K] row-major fp16.
//   grid (NM/BM, NF/BN1, NE); 8 warps 4(m)x2(n); warp tile 32x32 per output.
// smem tile: row r, 16B chunk c (0..7; chunk c = k c*8..c*8+7):
//   off = r*128 + ((c ^ (r & 7)) << 4)
// ---------------------------------------------------------------------------
__global__ void __launch_bounds__(NT, 2)
gemm1_swiglu(const __half* __restrict__ Ag, const __half* __restrict__ B1g,
             const __half* __restrict__ B3g, __half* __restrict__ Hg) {
    extern __shared__ char smc[];
    const int e  = blockIdx.z;
    const int m0 = blockIdx.x * BM;
    const int n0 = blockIdx.y * BN1;

    const __half* A  = Ag  + (size_t)e * NM * NH;
    const __half* B1 = B1g + (size_t)e * (size_t)NF * NH;
    const __half* B3 = B3g + (size_t)e * (size_t)NF * NH;
    __half*       H  = Hg  + (size_t)e * (size_t)NM * NF;

    const int tid  = threadIdx.x;
    const int warp = tid >> 5;
    const int l    = tid & 31;
    const int wm   = warp >> 1;      // m rows wm*32
    const int wn   = warp & 1;       // n cols wn*32
    const int lr7  = l & 7;

    const uint32_t smem0 = (uint32_t)__cvta_generic_to_shared(smc);

    // ldmatrix x4 lane geometry (b16 8x8 tiles)
    const int a_row = wm * 32 + ((l >> 3) & 1) * 8 + lr7;  // + mt*16
    const int a_cb  = (l >> 4) & 1;                         // lo/hi k8 chunk
    const int b_row = wn * 32 + ((l >> 4) & 1) * 8 + lr7;  // + ntl*16
    const int b_cb  = (l >> 3) & 1;

    const int f_row = tid >> 3;      // fill: +32 rows/step
    const int f_c   = tid & 7;

    float ac1[2][4][4], ac3[2][4][4];
#pragma unroll
    for (int i = 0; i < 2; i++)
#pragma unroll
        for (int j = 0; j < 4; j++)
#pragma unroll
            for (int t = 0; t < 4; t++) { ac1[i][j][t] = 0.f; ac3[i][j][t] = 0.f; }

    auto fill = [&](int st, int kt) {
        uint32_t sa  = smem0 + st * STG1_B;
        uint32_t sb1 = sa + TILE_A;
        uint32_t sb3 = sb1 + TILE_B1;
#pragma unroll
        for (int i = 0; i < 4; i++) {
            int row = f_row + i * 32;
            uint32_t off = row * 128 + ((f_c ^ (row & 7)) << 4);
            cp16(sa + off, A + (size_t)(m0 + row) * NH + kt + f_c * 8);
        }
#pragma unroll
        for (int i = 0; i < 2; i++) {
            int row = f_row + i * 32;
            uint32_t off = row * 128 + ((f_c ^ (row & 7)) << 4);
            size_t g = (size_t)(n0 + row) * NH + kt + f_c * 8;
            cp16(sb1 + off, B1 + g);
            cp16(sb3 + off, B3 + g);
        }
    };

    const int NIT = NH / BK;   // 32
    fill(0, 0);  cp_commit();
    fill(1, BK); cp_commit();

    for (int it = 0; it < NIT; it++) {
        cp_wait<1>();
        __syncthreads();

        int nt = it + 2;
        if (nt < NIT) fill(nt % STAGES, nt * BK);
        cp_commit();

        uint32_t sa  = smem0 + (it % STAGES) * STG1_B;
        uint32_t sb1 = sa + TILE_A;
        uint32_t sb3 = sb1 + TILE_B1;

#pragma unroll
        for (int kk = 0; kk < 4; kk++) {        // k16 steps
            uint32_t a[2][4], b1[2][4], b3[2][4];
#pragma unroll
            for (int mt = 0; mt < 2; mt++) {
                int row = a_row + mt * 16;
                int ch  = 2 * kk + a_cb;
                ldm4(a[mt][0], a[mt][1], a[mt][2], a[mt][3],
                     sa + row * 128 + ((ch ^ lr7) << 4));
            }
#pragma unroll
            for (int ntl = 0; ntl < 2; ntl++) {
                int row = b_row + ntl * 16;
                int ch  = 2 * kk + b_cb;
                uint32_t so = row * 128 + ((ch ^ lr7) << 4);
                ldm4(b1[ntl][0], b1[ntl][1], b1[ntl][2], b1[ntl][3], sb1 + so);
                ldm4(b3[ntl][0], b3[ntl][1], b3[ntl][2], b3[ntl][3], sb3 + so);
            }
#pragma unroll
            for (int mt = 0; mt < 2; mt++)
#pragma unroll
                for (int ntl = 0; ntl < 2; ntl++) {
                    mma_f16(ac1[mt][2 * ntl + 0], a[mt], b1[ntl][0], b1[ntl][1]);
                    mma_f16(ac1[mt][2 * ntl + 1], a[mt], b1[ntl][2], b1[ntl][3]);
                    mma_f16(ac3[mt][2 * ntl + 0], a[mt], b3[ntl][0], b3[ntl][1]);
                    mma_f16(ac3[mt][2 * ntl + 1], a[mt], b3[ntl][2], b3[ntl][3]);
                }
        }
    }

    // SwiGLU epilogue (identical fragment mappings), store fp16 hidden.
    const int erow = m0 + wm * 32 + (l >> 2);
    const int ecol = n0 + wn * 32 + 2 * (l & 3);
#pragma unroll
    for (int mt = 0; mt < 2; mt++)
#pragma unroll
        for (int j = 0; j < 4; j++) {
            float v0 = ac1[mt][j][0], v1 = ac1[mt][j][1];
            float v2 = ac1[mt][j][2], v3 = ac1[mt][j][3];
            float h0 = v0 / (1.0f + __expf(-v0)) * ac3[mt][j][0];
            float h1 = v1 / (1.0f + __expf(-v1)) * ac3[mt][j][1];
            float h2 = v2 / (1.0f + __expf(-v2)) * ac3[mt][j][2];
            float h3 = v3 / (1.0f + __expf(-v3)) * ac3[mt][j][3];
            __half* p0 = H + (size_t)(erow + mt * 16) * NF + ecol + j * 8;
            *reinterpret_cast<__half2*>(p0)          = __floats2half2_rn(h0, h1);
            *reinterpret_cast<__half2*>(p0 + 8 * NF) = __floats2half2_rn(h2, h3);
        }
}

// ---------------------------------------------------------------------------
// GEMM2: out = hid * w2^T   A [M,K=F] fp16, B [N=H,K=F] fp16, C fp32.
//   grid (NM/BM, NH/BN2, NE); warp tile 32x64.
// ---------------------------------------------------------------------------
__global__ void __launch_bounds__(NT, 2)
gemm_f16(const __half* __restrict__ Ag, const __half* __restrict__ Bg,
         float* __restrict__ Cg, int N, int K) {
    extern __shared__ char smc[];
    const int e  = blockIdx.z;
    const int m0 = blockIdx.x * BM;
    const int n0 = blockIdx.y * BN2;

    const __half* A = Ag + (size_t)e * NM * K;
    const __half* B = Bg + (size_t)e * (size_t)N * K;
    float*        C = Cg + (size_t)e * NM * N;

    const int tid  = threadIdx.x;
    const int warp = tid >> 5;
    const int l    = tid & 31;
    const int wm   = warp >> 1;
    const int wn   = warp & 1;       // cols wn*64
    const int lr7  = l & 7;

    const uint32_t smem0 = (uint32_t)__cvta_generic_to_shared(smc);

    const int a_row = wm * 32 + ((l >> 3) & 1) * 8 + lr7;
    const int a_cb  = (l >> 4) & 1;
    const int b_row = wn * 64 + ((l >> 4) & 1) * 8 + lr7;
    const int b_cb  = (l >> 3) & 1;

    const int f_row = tid >> 3;
    const int f_c   = tid & 7;

    float acc[2][8][4];
#pragma unroll
    for (int i = 0; i < 2; i++)
#pragma unroll
        for (int j = 0; j < 8; j++)
#pragma unroll
            for (int t = 0; t < 4; t++) acc[i][j][t] = 0.0f;

    auto fill = [&](int st, int kt) {
        uint32_t sa = smem0 + st * STG2_B;
        uint32_t sb = sa + TILE_A;
#pragma unroll
        for (int i = 0; i < 4; i++) {
            int row = f_row + i * 32;
            uint32_t off = row * 128 + ((f_c ^ (row & 7)) << 4);
            cp16(sa + off, A + (size_t)(m0 + row) * K + kt + f_c * 8);
            cp16(sb + off, B + (size_t)(n0 + row) * K + kt + f_c * 8);
        }
    };

    const int NIT = K / BK;   // 112
    fill(0, 0);  cp_commit();
    fill(1, BK); cp_commit();

    for (int it = 0; it < NIT; it++) {
        cp_wait<1>();
        __syncthreads();

        int nt = it + 2;
        if (nt < NIT) fill(nt % STAGES, nt * BK);
        cp_commit();

        uint32_t sa = smem0 + (it % STAGES) * STG2_B;
        uint32_t sb = sa + TILE_A;

#pragma unroll
        for (int kk = 0; kk < 4; kk++) {
            uint32_t a[2][4], b[4][4];
#pragma unroll
            for (int mt = 0; mt < 2; mt++) {
                int row = a_row + mt * 16;
                int ch  = 2 * kk + a_cb;
                ldm4(a[mt][0], a[mt][1], a[mt][2], a[mt][3],
                     sa + row * 128 + ((ch ^ lr7) << 4));
            }
#pragma unroll
            for (int ntl = 0; ntl < 4; ntl++) {
                int row = b_row + ntl * 16;
                int ch  = 2 * kk + b_cb;
                ldm4(b[ntl][0], b[ntl][1], b[ntl][2], b[ntl][3],
                     sb + row * 128 + ((ch ^ lr7) << 4));
            }
#pragma unroll
            for (int mt = 0; mt < 2; mt++)
#pragma unroll
                for (int ntl = 0; ntl < 4; ntl++) {
                    mma_f16(acc[mt][2 * ntl + 0], a[mt], b[ntl][0], b[ntl][1]);
                    mma_f16(acc[mt][2 * ntl + 1], a[mt], b[ntl][2], b[ntl][3]);
                }
        }
    }

    const int erow = m0 + wm * 32 + (l >> 2);
    const int ecol = n0 + wn * 64 + 2 * (l & 3);
#pragma unroll
    for (int mt = 0; mt < 2; mt++)
#pragma unroll
        for (int j = 0; j < 8; j++) {
            float* p0 = C + (size_t)(erow + mt * 16) * N + ecol + j * 8;
            *reinterpret_cast<float2*>(p0)         = make_float2(acc[mt][j][0], acc[mt][j][1]);
            *reinterpret_cast<float2*>(p0 + 8 * N) = make_float2(acc[mt][j][2], acc[mt][j][3]);
        }
}

// ---------------------------------------------------------------------------
// Launch
// ---------------------------------------------------------------------------
extern "C" void kernel_launch(void* const* d_in, const int* in_sizes, int n_in,
                              void* d_out, int out_size) {
    const float* x  = (const float*)d_in[0];   // (E, M, H)
    const float* w1 = (const float*)d_in[1];   // (E, H, F)
    const float* w2 = (const float*)d_in[2];   // (E, F, H)
    const float* w3 = (const float*)d_in[3];   // (E, H, F)
    float* out = (float*)d_out;                // (E, M, H)

    cudaFuncSetAttribute(gemm1_swiglu,
                         cudaFuncAttributeMaxDynamicSharedMemorySize, SMEM1);
    cudaFuncSetAttribute(gemm_f16,
                         cudaFuncAttributeMaxDynamicSharedMemorySize, SMEM2);

    void *pxc, *pw1, *pw2, *pw3, *ph;
    cudaGetSymbolAddress(&pxc, g_xc);
    cudaGetSymbolAddress(&pw1, g_w1t);
    cudaGetSymbolAddress(&pw2, g_w2t);
    cudaGetSymbolAddress(&pw3, g_w3t);
    cudaGetSymbolAddress(&ph,  g_hid);

    const int nx4 = NE * NM * NH / 4;
    conv_x<<<(nx4 + 255) / 256, 256>>>((const float4*)x, (__half2*)pxc, nx4);

    dim3 tb(32, 8);
    conv_t<<<dim3(NF / 32, NH / 32, NE), tb>>>(w1, (__half*)pw1, NH, NF); // ->[F,H]
    conv_t<<<dim3(NF / 32, NH / 32, NE), tb>>>(w3, (__half*)pw3, NH, NF); // ->[F,H]
    conv_t<<<dim3(NH / 32, NF / 32, NE), tb>>>(w2, (__half*)pw2, NF, NH); // ->[H,F]

    // fused: hid = fp16( silu(x*w1^T) * (x*w3^T) )
    dim3 g1(NM / BM, NF / BN1, NE);   // 16 x 112 x 8
    gemm1_swiglu<<<g1, NT, SMEM1>>>((const __half*)pxc, (const __half*)pw1,
                                    (const __half*)pw3, (__half*)ph);

    // out = hid * w2^T
    dim3 g2(NM / BM, NH / BN2, NE);   // 16 x 16 x 8
    gemm_f16<<<g2, NT, SMEM2>>>((const __half*)ph, (const __half*)pw2,
                                out, NH, NF);
}